// round 12
// baseline (speedup 1.0000x reference)
#include <cuda_runtime.h>
#include <cstdint>
#include <cstddef>

// Problem dims (fixed)
#define NSAMP 2048
#define JDIM  192
#define KDIM  192
#define R1D   256
#define R2D   48
#define R3D   48

#define PREP_BLOCKS 1154   // 576 Gt-transpose + 576 Grt-transpose + 2 softmax

// ---------------------------------------------------------------------------
// Scratch (__device__ globals; no allocation)
// ---------------------------------------------------------------------------
__device__ __align__(16) float    g_buf2[(size_t)NSAMP * R2D * R3D];    // Y then S (18MB)
__device__ __align__(16) float    g_Amat[(size_t)NSAMP * R1D];
__device__ __align__(16) float    g_smA [(size_t)NSAMP * R1D];
__device__ __align__(16) uint32_t g_smBT [JDIM * R2D];     // tf32 softmax(B) (192x48)
__device__ __align__(16) uint32_t g_smCT [KDIM * R3D];     // tf32 softmax(C) (192x48)
__device__ __align__(16) uint32_t g_Gt   [R1D * 2304];     // tf32 G_inv^T (256x2304)
__device__ __align__(16) uint32_t g_Grt  [2304 * R1D];     // tf32 relu(G)^T (2304x256)

// ---------------------------------------------------------------------------
// tf32 helpers
// ---------------------------------------------------------------------------
__device__ __forceinline__ uint32_t cvt_tf32(float x) {
    uint32_t r;
    asm("cvt.rna.tf32.f32 %0, %1;" : "=r"(r) : "f"(x));
    return r;
}

__device__ __forceinline__ void mma_tf32(float* d, const uint32_t* a, const uint32_t* b) {
    asm volatile(
        "mma.sync.aligned.m16n8k8.row.col.f32.tf32.tf32.f32 "
        "{%0,%1,%2,%3},{%4,%5,%6,%7},{%8,%9},{%0,%1,%2,%3};"
        : "+f"(d[0]), "+f"(d[1]), "+f"(d[2]), "+f"(d[3])
        : "r"(a[0]), "r"(a[1]), "r"(a[2]), "r"(a[3]), "r"(b[0]), "r"(b[1]));
}

__device__ __forceinline__ void cp_async16(uint32_t smem_dst, const void* gsrc) {
    asm volatile("cp.async.cg.shared.global [%0], [%1], 16;" :: "r"(smem_dst), "l"(gsrc));
}

// ---------------------------------------------------------------------------
// Fused encode + prep: grid = PREP_BLOCKS + 2048, 192 threads, 3 CTAs/SM.
// ---------------------------------------------------------------------------
#define ENC_SMEM_U32 (48*196 + 48*196)
__global__ void __launch_bounds__(192, 3) k_enc(
    const float* __restrict__ X, const float* __restrict__ Binv,
    const float* __restrict__ Cinv, float* __restrict__ Y,
    const float* __restrict__ Gi, const float* __restrict__ G,
    const float* __restrict__ Bm, const float* __restrict__ Cm,
    uint32_t* __restrict__ Gt, uint32_t* __restrict__ Grt,
    uint32_t* __restrict__ smBT, uint32_t* __restrict__ smCT)
{
    extern __shared__ uint32_t sme[];
    const int tid = threadIdx.x;

    // ---------------- prep branch ----------------
    if (blockIdx.x < PREP_BLOCKS) {
        int b = blockIdx.x;
        float* tile = (float*)sme;   // 32x33 floats
        if (b < 576) {
            int br = b >> 3, bc = b & 7;
            for (int i = tid; i < 1024; i += 192) {
                int r = i >> 5, c = i & 31;
                tile[r * 33 + c] = Gi[(size_t)(br * 32 + r) * 256 + bc * 32 + c];
            }
            __syncthreads();
            for (int i = tid; i < 1024; i += 192) {
                int r = i >> 5, c = i & 31;
                Gt[(size_t)(bc * 32 + r) * 2304 + br * 32 + c] = cvt_tf32(tile[c * 33 + r]);
            }
        } else if (b < 1152) {
            int b2 = b - 576;
            int br = b2 & 7, bc = b2 >> 3;
            for (int i = tid; i < 1024; i += 192) {
                int r = i >> 5, c = i & 31;
                tile[r * 33 + c] = G[(size_t)(br * 32 + r) * 2304 + bc * 32 + c];
            }
            __syncthreads();
            for (int i = tid; i < 1024; i += 192) {
                int r = i >> 5, c = i & 31;
                Grt[(size_t)(bc * 32 + r) * 256 + br * 32 + c] =
                    cvt_tf32(fmaxf(tile[c * 33 + r], 0.f));
            }
        } else {
            const float* in = (b == 1152) ? Bm : Cm;
            uint32_t* outp = (b == 1152) ? smBT : smCT;
            const float* p = in + tid * 48;
            float m = -1e30f;
            #pragma unroll
            for (int j = 0; j < 48; j++) m = fmaxf(m, p[j]);
            float s = 0.f;
            #pragma unroll
            for (int j = 0; j < 48; j++) s += __expf(p[j] - m);
            float inv = 1.f / s;
            #pragma unroll
            for (int j = 0; j < 48; j++)
                outp[tid * 48 + j] = cvt_tf32(__expf(p[j] - m) * inv);
        }
        return;
    }

    // ---------------- encode branch (R10-measured) ----------------
    uint32_t* Fs = sme;                     // 48*196 tf32: Binv, later Cinv
    float*    Xf = (float*)(sme + 48*196);  // 2 x 192 x 20 fp32
    uint32_t* Ts = sme + 48*196;            // later: T^T 48x196 tf32

    const int n = blockIdx.x - PREP_BLOCKS;
    const int w = tid >> 5, lane = tid & 31;
    const int lr = lane >> 2, lc = lane & 3;

    for (int i = tid; i < 2304; i += 192) {
        int r = i / 48, c = (i % 48) * 4;
        float4 v = *(const float4*)(Binv + r * 192 + c);
        uint32_t* p = &Fs[r * 196 + c];
        p[0] = cvt_tf32(v.x); p[1] = cvt_tf32(v.y);
        p[2] = cvt_tf32(v.z); p[3] = cvt_tf32(v.w);
    }

    const uint32_t xs_base = (uint32_t)__cvta_generic_to_shared(Xf);
    const float* Xn = X + (size_t)n * 36864;

    auto load_chunk = [&](int ck, int buf) {
        const float* src = Xn + ck * 16;
        #pragma unroll
        for (int i = tid; i < 768; i += 192) {
            int row = i >> 2, seg = i & 3;
            cp_async16(xs_base + (buf * 3840 + row * 20 + seg * 4) * 4,
                       src + row * 192 + seg * 4);
        }
        asm volatile("cp.async.commit_group;");
    };

    load_chunk(0, 0);

    float acc[2][6][4];
    #pragma unroll
    for (int i = 0; i < 2; i++)
        #pragma unroll
        for (int j = 0; j < 6; j++)
            #pragma unroll
            for (int d = 0; d < 4; d++) acc[i][j][d] = 0.f;

    for (int ck = 0; ck < 12; ck++) {
        asm volatile("cp.async.wait_group 0;" ::: "memory");
        __syncthreads();
        if (ck < 11) load_chunk(ck + 1, (ck + 1) & 1);
        const float* Xb = Xf + ((ck & 1) ? 3840 : 0);

        #pragma unroll
        for (int kk = 0; kk < 16; kk += 8) {
            uint32_t af[2][4], bf[6][2];
            #pragma unroll
            for (int mt = 0; mt < 2; mt++) {
                const float* pa = Xb + (w * 32 + mt * 16 + lr) * 20 + kk + lc;
                af[mt][0] = cvt_tf32(pa[0]);
                af[mt][1] = cvt_tf32(pa[160]);
                af[mt][2] = cvt_tf32(pa[4]);
                af[mt][3] = cvt_tf32(pa[164]);
            }
            #pragma unroll
            for (int nt = 0; nt < 6; nt++) {
                const uint32_t* pb = &Fs[(nt * 8 + lr) * 196 + ck * 16 + kk + lc];
                bf[nt][0] = pb[0]; bf[nt][1] = pb[4];
            }
            #pragma unroll
            for (int mt = 0; mt < 2; mt++)
                #pragma unroll
                for (int nt = 0; nt < 6; nt++)
                    mma_tf32(acc[mt][nt], af[mt], bf[nt]);
        }
    }
    __syncthreads();

    #pragma unroll
    for (int mt = 0; mt < 2; mt++) {
        int k0 = w * 32 + mt * 16 + lr;
        #pragma unroll
        for (int nt = 0; nt < 6; nt++) {
            int r2 = nt * 8 + 2 * lc;
            Ts[r2 * 196 + k0]           = cvt_tf32(acc[mt][nt][0]);
            Ts[(r2 + 1) * 196 + k0]     = cvt_tf32(acc[mt][nt][1]);
            Ts[r2 * 196 + k0 + 8]       = cvt_tf32(acc[mt][nt][2]);
            Ts[(r2 + 1) * 196 + k0 + 8] = cvt_tf32(acc[mt][nt][3]);
        }
    }
    for (int i = tid; i < 2304; i += 192) {
        int r = i / 48, c = (i % 48) * 4;
        float4 v = *(const float4*)(Cinv + r * 192 + c);
        uint32_t* p = &Fs[r * 196 + c];
        p[0] = cvt_tf32(v.x); p[1] = cvt_tf32(v.y);
        p[2] = cvt_tf32(v.z); p[3] = cvt_tf32(v.w);
    }
    __syncthreads();

    const int mt2 = w % 3, nh = w / 3;
    float a2[3][4];
    #pragma unroll
    for (int i = 0; i < 3; i++)
        #pragma unroll
        for (int d = 0; d < 4; d++) a2[i][d] = 0.f;

    #pragma unroll 8
    for (int kk = 0; kk < 192; kk += 8) {
        uint32_t af[4];
        const uint32_t* pa = &Fs[(mt2 * 16 + lr) * 196 + kk + lc];
        af[0] = pa[0]; af[1] = pa[1568]; af[2] = pa[4]; af[3] = pa[1572];
        #pragma unroll
        for (int nt = 0; nt < 3; nt++) {
            const uint32_t* pb = &Ts[(nh * 24 + nt * 8 + lr) * 196 + kk + lc];
            uint32_t bf[2] = { pb[0], pb[4] };
            mma_tf32(a2[nt], af, bf);
        }
    }
    float* Yn = Y + (size_t)n * 2304;
    #pragma unroll
    for (int nt = 0; nt < 3; nt++) {
        int r3 = mt2 * 16 + lr;
        int r2 = nh * 24 + nt * 8 + 2 * lc;
        *(float2*)(Yn + r3 * 48 + r2)       = make_float2(a2[nt][0], a2[nt][1]);
        *(float2*)(Yn + (r3 + 8) * 48 + r2) = make_float2(a2[nt][2], a2[nt][3]);
    }
}

// ---------------------------------------------------------------------------
// Pipelined tf32 TC GEMM:  C[M,N] = A[M,K] (fp32) @ B[N,K]^T (tf32)
// Wait-then-issue double buffering (R7/R10-measured).
// ---------------------------------------------------------------------------
template <int BM, int BN, int BK, int MW, int NW>
__global__ void __launch_bounds__(256) k_gemm_tc_p(
    const float* __restrict__ A, const uint32_t* __restrict__ B,
    float* __restrict__ C, int M, int N, int K)
{
    constexpr int WM = BM / MW, WN = BN / NW;
    constexpr int MT = WM / 16, NT = WN / 8;
    constexpr int LDSS = BK + 4;
    extern __shared__ uint32_t smg[];
    float*    As = (float*)smg;              // 2 x BM x LDSS
    uint32_t* Bs = smg + 2 * BM * LDSS;      // 2 x BN x LDSS

    const int tid  = threadIdx.x;
    const int lane = tid & 31, warp = tid >> 5;
    const int wm = (warp / NW) * WM;
    const int wn = (warp % NW) * WN;
    const int m0 = blockIdx.y * BM;
    const int n0 = blockIdx.x * BN;
    const int lr = lane >> 2, lc = lane & 3;

    const uint32_t as_base = (uint32_t)__cvta_generic_to_shared(As);
    const uint32_t bs_base = (uint32_t)__cvta_generic_to_shared(Bs);

    auto load_stage = [&](int it, int buf) {
        const int k0 = it * BK;
        #pragma unroll
        for (int i = tid; i < BM * BK / 4; i += 256) {
            int r = i / (BK / 4), s = (i % (BK / 4)) * 4;
            cp_async16(as_base + (buf * BM * LDSS + r * LDSS + s) * 4,
                       A + (size_t)(m0 + r) * K + k0 + s);
        }
        #pragma unroll
        for (int i = tid; i < BN * BK / 4; i += 256) {
            int r = i / (BK / 4), s = (i % (BK / 4)) * 4;
            cp_async16(bs_base + (buf * BN * LDSS + r * LDSS + s) * 4,
                       B + (size_t)(n0 + r) * K + k0 + s);
        }
        asm volatile("cp.async.commit_group;");
    };

    float acc[MT][NT][4];
    #pragma unroll
    for (int i = 0; i < MT; i++)
        #pragma unroll
        for (int j = 0; j < NT; j++)
            #pragma unroll
            for (int d = 0; d < 4; d++) acc[i][j][d] = 0.f;

    load_stage(0, 0);
    const int iters = K / BK;

    for (int it = 0; it < iters; it++) {
        asm volatile("cp.async.wait_group 0;" ::: "memory");
        __syncthreads();
        if (it + 1 < iters) load_stage(it + 1, (it + 1) & 1);
        const float*    Ab = As + (it & 1) * BM * LDSS;
        const uint32_t* Bb = Bs + (it & 1) * BN * LDSS;

        #pragma unroll
        for (int kk = 0; kk < BK; kk += 8) {
            uint32_t af[MT][4], bf[NT][2];
            #pragma unroll
            for (int mt = 0; mt < MT; mt++) {
                const float* pa = Ab + (wm + mt * 16 + lr) * LDSS + kk + lc;
                af[mt][0] = cvt_tf32(pa[0]);
                af[mt][1] = cvt_tf32(pa[8 * LDSS]);
                af[mt][2] = cvt_tf32(pa[4]);
                af[mt][3] = cvt_tf32(pa[8 * LDSS + 4]);
            }
            #pragma unroll
            for (int nt = 0; nt < NT; nt++) {
                const uint32_t* pb = Bb + (wn + nt * 8 + lr) * LDSS + kk + lc;
                bf[nt][0] = pb[0];
                bf[nt][1] = pb[4];
            }
            #pragma unroll
            for (int mt = 0; mt < MT; mt++)
                #pragma unroll
                for (int nt = 0; nt < NT; nt++)
                    mma_tf32(acc[mt][nt], af[mt], bf[nt]);
        }
        __syncthreads();
    }

    #pragma unroll
    for (int mt = 0; mt < MT; mt++) {
        int r0 = m0 + wm + mt * 16 + lr;
        #pragma unroll
        for (int nt = 0; nt < NT; nt++) {
            int c0 = n0 + wn + nt * 8 + 2 * lc;
            *(float2*)(C + (size_t)r0 * N + c0)       = make_float2(acc[mt][nt][0], acc[mt][nt][1]);
            *(float2*)(C + (size_t)(r0 + 8) * N + c0) = make_float2(acc[mt][nt][2], acc[mt][nt][3]);
        }
    }
}

#define GEMMA_SMEM ((2*64*68 + 2*32*68) * 4)
#define GEMMS_SMEM ((2*128*36 + 2*64*36) * 4)

// ---------------------------------------------------------------------------
// Row softmax for A (2048 x 256): warp-per-row, shfl-only.
// ---------------------------------------------------------------------------
__global__ void __launch_bounds__(256) k_softmaxA(
    const float* __restrict__ A, float* __restrict__ out)
{
    const int w = threadIdx.x >> 5, lane = threadIdx.x & 31;
    const int n = blockIdx.x * 8 + w;
    const float4* a4 = (const float4*)(A + (size_t)n * 256);
    float4 v0 = a4[lane];
    float4 v1 = a4[lane + 32];

    float m = fmaxf(fmaxf(fmaxf(v0.x, v0.y), fmaxf(v0.z, v0.w)),
                    fmaxf(fmaxf(v1.x, v1.y), fmaxf(v1.z, v1.w)));
    #pragma unroll
    for (int o = 16; o > 0; o >>= 1) m = fmaxf(m, __shfl_xor_sync(0xffffffffu, m, o));

    float e0 = __expf(v0.x - m), e1 = __expf(v0.y - m);
    float e2 = __expf(v0.z - m), e3 = __expf(v0.w - m);
    float e4 = __expf(v1.x - m), e5 = __expf(v1.y - m);
    float e6 = __expf(v1.z - m), e7 = __expf(v1.w - m);
    float s = ((e0 + e1) + (e2 + e3)) + ((e4 + e5) + (e6 + e7));
    #pragma unroll
    for (int o = 16; o > 0; o >>= 1) s += __shfl_xor_sync(0xffffffffu, s, o);
    float inv = 1.f / s;

    float4* o4 = (float4*)(out + (size_t)n * 256);
    o4[lane]      = make_float4(e0 * inv, e1 * inv, e2 * inv, e3 * inv);
    o4[lane + 32] = make_float4(e4 * inv, e5 * inv, e6 * inv, e7 * inv);
}

// ---------------------------------------------------------------------------
// Fused decode: one CTA per sample n, 192 threads = 6 warps, 3 CTAs/SM.
// (R10-measured: stride-48 XOR swizzle, St/Bsm aliased, register-lean stage2.)
// ---------------------------------------------------------------------------
#define DEC_SMEM_U32 (192*48 + 192*48)
__global__ void __launch_bounds__(192, 3) k_dec(
    const float* __restrict__ S, const uint32_t* __restrict__ smB,
    const uint32_t* __restrict__ smC, float* __restrict__ out)
{
    extern __shared__ uint32_t smd[];
    uint32_t* Cs = smd;              // smC [k][r3] swizzled; then Ua [k][r2]
    uint32_t* R2 = smd + 192 * 48;   // St (48x48) then Bsm (192x48), swizzled

    const int n = blockIdx.x, tid = threadIdx.x;
    const int w = tid >> 5, lane = tid & 31;
    const int lr = lane >> 2, lc = lane & 3;
    const int sw = (lr & 6) << 1;

    for (int i = tid; i < 2304; i += 192) {
        int r = i / 12, c = (i % 12) * 4;
        uint4 v = *(const uint4*)(smC + r * 48 + c);
        uint32_t* p = &Cs[r * 48 + (c ^ ((r & 6) << 1))];
        p[0] = v.x; p[1] = v.y; p[2] = v.z; p[3] = v.w;
    }
    const float* Sn = S + (size_t)n * 2304;
    for (int i = tid; i < 576; i += 192) {
        int r3 = i / 12, r2 = (i % 12) * 4;
        float4 v = *(const float4*)(Sn + r3 * 48 + r2);
        R2[(r2 + 0) * 48 + (r3 ^ (((r2 + 0) & 6) << 1))] = cvt_tf32(v.x);
        R2[(r2 + 1) * 48 + (r3 ^ (((r2 + 1) & 6) << 1))] = cvt_tf32(v.y);
        R2[(r2 + 2) * 48 + (r3 ^ (((r2 + 2) & 6) << 1))] = cvt_tf32(v.z);
        R2[(r2 + 3) * 48 + (r3 ^ (((r2 + 3) & 6) << 1))] = cvt_tf32(v.w);
    }
    __syncthreads();

    float a1[2][6][4];
    #pragma unroll
    for (int i = 0; i < 2; i++)
        #pragma unroll
        for (int j = 0; j < 6; j++)
            #pragma unroll
            for (int d = 0; d < 4; d++) a1[i][j][d] = 0.f;

    #pragma unroll
    for (int kk = 0; kk < 48; kk += 8) {
        const int c0 = (kk ^ sw) + lc;
        const int c1 = ((kk + 4) ^ sw) + lc;
        uint32_t af[2][4], bf[6][2];
        #pragma unroll
        for (int mt = 0; mt < 2; mt++) {
            const uint32_t* pa = &Cs[(w * 32 + mt * 16 + lr) * 48];
            af[mt][0] = pa[c0]; af[mt][1] = pa[384 + c0];
            af[mt][2] = pa[c1]; af[mt][3] = pa[384 + c1];
        }
        #pragma unroll
        for (int nt = 0; nt < 6; nt++) {
            const uint32_t* pb = &R2[(nt * 8 + lr) * 48];
            bf[nt][0] = pb[c0]; bf[nt][1] = pb[c1];
        }
        #pragma unroll
        for (int mt = 0; mt < 2; mt++)
            #pragma unroll
            for (int nt = 0; nt < 6; nt++)
                mma_tf32(a1[mt][nt], af[mt], bf[nt]);
    }
    __syncthreads();

    #pragma unroll
    for (int mt = 0; mt < 2; mt++) {
        int k0 = w * 32 + mt * 16 + lr;
        #pragma unroll
        for (int nt = 0; nt < 6; nt++) {
            int cc = ((nt * 8 + 2 * lc) ^ sw);
            Cs[k0 * 48 + cc]           = cvt_tf32(a1[mt][nt][0]);
            Cs[k0 * 48 + cc + 1]       = cvt_tf32(a1[mt][nt][1]);
            Cs[(k0 + 8) * 48 + cc]     = cvt_tf32(a1[mt][nt][2]);
            Cs[(k0 + 8) * 48 + cc + 1] = cvt_tf32(a1[mt][nt][3]);
        }
    }
    for (int i = tid; i < 2304; i += 192) {
        int r = i / 12, c = (i % 12) * 4;
        uint4 v = *(const uint4*)(smB + r * 48 + c);
        uint32_t* p = &R2[r * 48 + (c ^ ((r & 6) << 1))];
        p[0] = v.x; p[1] = v.y; p[2] = v.z; p[3] = v.w;
    }
    __syncthreads();

    float* on = out + (size_t)n * 36864;
    const int wm = (w % 3) * 64;
    const int nb = (w / 3) * 24;
    #pragma unroll 1
    for (int np = 0; np < 4; np++) {
        const int wn = nb + np * 48;
        #pragma unroll 1
        for (int mp = 0; mp < 2; mp++) {
            const int mbase = wm + mp * 32;
            float a2[2][3][4];
            #pragma unroll
            for (int i = 0; i < 2; i++)
                #pragma unroll
                for (int j = 0; j < 3; j++)
                    #pragma unroll
                    for (int d = 0; d < 4; d++) a2[i][j][d] = 0.f;

            #pragma unroll
            for (int kk = 0; kk < 48; kk += 8) {
                const int c0 = (kk ^ sw) + lc;
                const int c1 = ((kk + 4) ^ sw) + lc;
                uint32_t af[2][4], bf[3][2];
                #pragma unroll
                for (int mt = 0; mt < 2; mt++) {
                    const uint32_t* pa = &Cs[(mbase + mt * 16 + lr) * 48];
                    af[mt][0] = pa[c0]; af[mt][1] = pa[384 + c0];
                    af[mt][2] = pa[c1]; af[mt][3] = pa[384 + c1];
                }
                #pragma unroll
                for (int nt = 0; nt < 3; nt++) {
                    const uint32_t* pb = &R2[(wn + nt * 8 + lr) * 48];
                    bf[nt][0] = pb[c0]; bf[nt][1] = pb[c1];
                }
                #pragma unroll
                for (int mt = 0; mt < 2; mt++)
                    #pragma unroll
                    for (int nt = 0; nt < 3; nt++)
                        mma_tf32(a2[mt][nt], af[mt], bf[nt]);
            }
            #pragma unroll
            for (int mt = 0; mt < 2; mt++) {
                int row = mbase + mt * 16 + lr;
                #pragma unroll
                for (int nt = 0; nt < 3; nt++) {
                    int col = wn + nt * 8 + 2 * lc;
                    *(float2*)(on + (size_t)row * 192 + col) =
                        make_float2(a2[mt][nt][0], a2[mt][nt][1]);
                    *(float2*)(on + (size_t)(row + 8) * 192 + col) =
                        make_float2(a2[mt][nt][2], a2[mt][nt][3]);
                }
            }
        }
    }
}

// ---------------------------------------------------------------------------
// Launch pipeline (default stream -> sequential; graph-capturable)
// ---------------------------------------------------------------------------
extern "C" void kernel_launch(void* const* d_in, const int* in_sizes, int n_in,
                              void* d_out, int out_size)
{
    const float* X     = (const float*)d_in[0];
    const float* B     = (const float*)d_in[1];
    const float* C     = (const float*)d_in[2];
    const float* G     = (const float*)d_in[3];
    const float* B_inv = (const float*)d_in[4];
    const float* C_inv = (const float*)d_in[5];
    const float* G_inv = (const float*)d_in[6];
    float* out = (float*)d_out;

    float *pBuf2, *pA, *pSmA;
    uint32_t *pSmBT, *pSmCT, *pGt, *pGrt;
    cudaGetSymbolAddress((void**)&pBuf2, g_buf2);
    cudaGetSymbolAddress((void**)&pA,    g_Amat);
    cudaGetSymbolAddress((void**)&pSmA,  g_smA);
    cudaGetSymbolAddress((void**)&pSmBT, g_smBT);
    cudaGetSymbolAddress((void**)&pSmCT, g_smCT);
    cudaGetSymbolAddress((void**)&pGt,   g_Gt);
    cudaGetSymbolAddress((void**)&pGrt,  g_Grt);

    cudaFuncSetAttribute(k_enc, cudaFuncAttributeMaxDynamicSharedMemorySize, ENC_SMEM_U32 * 4);
    cudaFuncSetAttribute(k_dec, cudaFuncAttributeMaxDynamicSharedMemorySize, DEC_SMEM_U32 * 4);
    cudaFuncSetAttribute((const void*)k_gemm_tc_p<64, 32, 64, 4, 2>,
                         cudaFuncAttributeMaxDynamicSharedMemorySize, GEMMA_SMEM);
    cudaFuncSetAttribute((const void*)k_gemm_tc_p<128, 64, 32, 4, 2>,
                         cudaFuncAttributeMaxDynamicSharedMemorySize, GEMMS_SMEM);

    // encode + prep in one launch
    k_enc<<<PREP_BLOCKS + NSAMP, 192, ENC_SMEM_U32 * 4>>>(
        X, B_inv, C_inv, pBuf2, G_inv, G, B, C, pGt, pGrt, pSmBT, pSmCT);

    // A = Y(2048x2304) @ G_inv(2304x256); softmax rows
    k_gemm_tc_p<64, 32, 64, 4, 2><<<dim3(8, 32), 256, GEMMA_SMEM>>>(
        pBuf2, pGt, pA, 2048, 256, 2304);
    k_softmaxA<<<256, 256>>>(pA, pSmA);

    // S = smA(2048x256) @ relu(G)(256x2304) — retiled 128x64 for 2 CTAs/SM
    k_gemm_tc_p<128, 64, 32, 4, 2><<<dim3(36, 16), 256, GEMMS_SMEM>>>(
        pSmA, pGrt, pBuf2, 2048, 2304, 256);

    // decode: out[n] = (smC @ S[n]) @ smB^T
    k_dec<<<2048, 192, DEC_SMEM_U32 * 4>>>(pBuf2, pSmBT, pSmCT, out);
}

// round 13
// speedup vs baseline: 1.0212x; 1.0212x over previous
#include <cuda_runtime.h>
#include <cstdint>
#include <cstddef>

// Problem dims (fixed)
#define NSAMP 2048
#define JDIM  192
#define KDIM  192
#define R1D   256
#define R2D   48
#define R3D   48

#define PREP_BLOCKS 1154   // 576 Gt-transpose + 576 Grt-transpose + 2 softmax

// ---------------------------------------------------------------------------
// Scratch (__device__ globals; no allocation)
// ---------------------------------------------------------------------------
__device__ __align__(16) float    g_buf2[(size_t)NSAMP * R2D * R3D];    // Y then S (18MB)
__device__ __align__(16) float    g_Amat[(size_t)NSAMP * R1D];
__device__ __align__(16) float    g_smA [(size_t)NSAMP * R1D];
__device__ __align__(16) uint32_t g_smBT [JDIM * R2D];     // tf32 softmax(B) (192x48)
__device__ __align__(16) uint32_t g_smCT [KDIM * R3D];     // tf32 softmax(C) (192x48)
__device__ __align__(16) uint32_t g_Gt   [R1D * 2304];     // tf32 G_inv^T (256x2304)
__device__ __align__(16) uint32_t g_Grt  [2304 * R1D];     // tf32 relu(G)^T (2304x256)

// ---------------------------------------------------------------------------
// tf32 helpers
// ---------------------------------------------------------------------------
__device__ __forceinline__ uint32_t cvt_tf32(float x) {
    uint32_t r;
    asm("cvt.rna.tf32.f32 %0, %1;" : "=r"(r) : "f"(x));
    return r;
}

__device__ __forceinline__ void mma_tf32(float* d, const uint32_t* a, const uint32_t* b) {
    asm volatile(
        "mma.sync.aligned.m16n8k8.row.col.f32.tf32.tf32.f32 "
        "{%0,%1,%2,%3},{%4,%5,%6,%7},{%8,%9},{%0,%1,%2,%3};"
        : "+f"(d[0]), "+f"(d[1]), "+f"(d[2]), "+f"(d[3])
        : "r"(a[0]), "r"(a[1]), "r"(a[2]), "r"(a[3]), "r"(b[0]), "r"(b[1]));
}

__device__ __forceinline__ void cp_async16(uint32_t smem_dst, const void* gsrc) {
    asm volatile("cp.async.cg.shared.global [%0], [%1], 16;" :: "r"(smem_dst), "l"(gsrc));
}

// ---------------------------------------------------------------------------
// Fused encode + prep: grid = PREP_BLOCKS + 2048, 192 threads, 3 CTAs/SM.
// ---------------------------------------------------------------------------
#define ENC_SMEM_U32 (48*196 + 48*196)
__global__ void __launch_bounds__(192, 3) k_enc(
    const float* __restrict__ X, const float* __restrict__ Binv,
    const float* __restrict__ Cinv, float* __restrict__ Y,
    const float* __restrict__ Gi, const float* __restrict__ G,
    const float* __restrict__ Bm, const float* __restrict__ Cm,
    uint32_t* __restrict__ Gt, uint32_t* __restrict__ Grt,
    uint32_t* __restrict__ smBT, uint32_t* __restrict__ smCT)
{
    extern __shared__ uint32_t sme[];
    const int tid = threadIdx.x;

    // ---------------- prep branch ----------------
    if (blockIdx.x < PREP_BLOCKS) {
        int b = blockIdx.x;
        float* tile = (float*)sme;   // 32x33 floats
        if (b < 576) {
            int br = b >> 3, bc = b & 7;
            for (int i = tid; i < 1024; i += 192) {
                int r = i >> 5, c = i & 31;
                tile[r * 33 + c] = Gi[(size_t)(br * 32 + r) * 256 + bc * 32 + c];
            }
            __syncthreads();
            for (int i = tid; i < 1024; i += 192) {
                int r = i >> 5, c = i & 31;
                Gt[(size_t)(bc * 32 + r) * 2304 + br * 32 + c] = cvt_tf32(tile[c * 33 + r]);
            }
        } else if (b < 1152) {
            int b2 = b - 576;
            int br = b2 & 7, bc = b2 >> 3;
            for (int i = tid; i < 1024; i += 192) {
                int r = i >> 5, c = i & 31;
                tile[r * 33 + c] = G[(size_t)(br * 32 + r) * 2304 + bc * 32 + c];
            }
            __syncthreads();
            for (int i = tid; i < 1024; i += 192) {
                int r = i >> 5, c = i & 31;
                Grt[(size_t)(bc * 32 + r) * 256 + br * 32 + c] =
                    cvt_tf32(fmaxf(tile[c * 33 + r], 0.f));
            }
        } else {
            const float* in = (b == 1152) ? Bm : Cm;
            uint32_t* outp = (b == 1152) ? smBT : smCT;
            const float* p = in + tid * 48;
            float m = -1e30f;
            #pragma unroll
            for (int j = 0; j < 48; j++) m = fmaxf(m, p[j]);
            float s = 0.f;
            #pragma unroll
            for (int j = 0; j < 48; j++) s += __expf(p[j] - m);
            float inv = 1.f / s;
            #pragma unroll
            for (int j = 0; j < 48; j++)
                outp[tid * 48 + j] = cvt_tf32(__expf(p[j] - m) * inv);
        }
        return;
    }

    // ---------------- encode branch ----------------
    uint32_t* Fs = sme;                     // 48*196 tf32: Binv, later Cinv
    float*    Xf = (float*)(sme + 48*196);  // 2 x 192 x 20 fp32
    uint32_t* Ts = sme + 48*196;            // later: T^T 48x196 tf32

    const int n = blockIdx.x - PREP_BLOCKS;
    const int w = tid >> 5, lane = tid & 31;
    const int lr = lane >> 2, lc = lane & 3;

    for (int i = tid; i < 2304; i += 192) {
        int r = i / 48, c = (i % 48) * 4;
        float4 v = *(const float4*)(Binv + r * 192 + c);
        uint32_t* p = &Fs[r * 196 + c];
        p[0] = cvt_tf32(v.x); p[1] = cvt_tf32(v.y);
        p[2] = cvt_tf32(v.z); p[3] = cvt_tf32(v.w);
    }

    const uint32_t xs_base = (uint32_t)__cvta_generic_to_shared(Xf);
    const float* Xn = X + (size_t)n * 36864;

    auto load_chunk = [&](int ck, int buf) {
        const float* src = Xn + ck * 16;
        #pragma unroll
        for (int i = tid; i < 768; i += 192) {
            int row = i >> 2, seg = i & 3;
            cp_async16(xs_base + (buf * 3840 + row * 20 + seg * 4) * 4,
                       src + row * 192 + seg * 4);
        }
        asm volatile("cp.async.commit_group;");
    };

    load_chunk(0, 0);

    float acc[2][6][4];
    #pragma unroll
    for (int i = 0; i < 2; i++)
        #pragma unroll
        for (int j = 0; j < 6; j++)
            #pragma unroll
            for (int d = 0; d < 4; d++) acc[i][j][d] = 0.f;

    // issue-before-wait: transfer of chunk ck+1 overlaps compute of chunk ck.
    for (int ck = 0; ck < 12; ck++) {
        if (ck < 11) {
            load_chunk(ck + 1, (ck + 1) & 1);
            asm volatile("cp.async.wait_group 1;" ::: "memory");  // chunk ck arrived
        } else {
            asm volatile("cp.async.wait_group 0;" ::: "memory");
        }
        __syncthreads();                       // chunk ck visible to all warps
        const float* Xb = Xf + ((ck & 1) ? 3840 : 0);

        #pragma unroll
        for (int kk = 0; kk < 16; kk += 8) {
            uint32_t af[2][4], bf[6][2];
            #pragma unroll
            for (int mt = 0; mt < 2; mt++) {
                const float* pa = Xb + (w * 32 + mt * 16 + lr) * 20 + kk + lc;
                af[mt][0] = cvt_tf32(pa[0]);
                af[mt][1] = cvt_tf32(pa[160]);
                af[mt][2] = cvt_tf32(pa[4]);
                af[mt][3] = cvt_tf32(pa[164]);
            }
            #pragma unroll
            for (int nt = 0; nt < 6; nt++) {
                const uint32_t* pb = &Fs[(nt * 8 + lr) * 196 + ck * 16 + kk + lc];
                bf[nt][0] = pb[0]; bf[nt][1] = pb[4];
            }
            #pragma unroll
            for (int mt = 0; mt < 2; mt++)
                #pragma unroll
                for (int nt = 0; nt < 6; nt++)
                    mma_tf32(acc[mt][nt], af[mt], bf[nt]);
        }
        __syncthreads();   // compute on buffer ck&1 done -> safe to overwrite next iter
    }

    // Store T transposed -> Ts[r2][k] (tf32, stride 196); overwrites X buffers
    #pragma unroll
    for (int mt = 0; mt < 2; mt++) {
        int k0 = w * 32 + mt * 16 + lr;
        #pragma unroll
        for (int nt = 0; nt < 6; nt++) {
            int r2 = nt * 8 + 2 * lc;
            Ts[r2 * 196 + k0]           = cvt_tf32(acc[mt][nt][0]);
            Ts[(r2 + 1) * 196 + k0]     = cvt_tf32(acc[mt][nt][1]);
            Ts[r2 * 196 + k0 + 8]       = cvt_tf32(acc[mt][nt][2]);
            Ts[(r2 + 1) * 196 + k0 + 8] = cvt_tf32(acc[mt][nt][3]);
        }
    }
    for (int i = tid; i < 2304; i += 192) {
        int r = i / 48, c = (i % 48) * 4;
        float4 v = *(const float4*)(Cinv + r * 192 + c);
        uint32_t* p = &Fs[r * 196 + c];
        p[0] = cvt_tf32(v.x); p[1] = cvt_tf32(v.y);
        p[2] = cvt_tf32(v.z); p[3] = cvt_tf32(v.w);
    }
    __syncthreads();

    const int mt2 = w % 3, nh = w / 3;
    float a2[3][4];
    #pragma unroll
    for (int i = 0; i < 3; i++)
        #pragma unroll
        for (int d = 0; d < 4; d++) a2[i][d] = 0.f;

    #pragma unroll 8
    for (int kk = 0; kk < 192; kk += 8) {
        uint32_t af[4];
        const uint32_t* pa = &Fs[(mt2 * 16 + lr) * 196 + kk + lc];
        af[0] = pa[0]; af[1] = pa[1568]; af[2] = pa[4]; af[3] = pa[1572];
        #pragma unroll
        for (int nt = 0; nt < 3; nt++) {
            const uint32_t* pb = &Ts[(nh * 24 + nt * 8 + lr) * 196 + kk + lc];
            uint32_t bf[2] = { pb[0], pb[4] };
            mma_tf32(a2[nt], af, bf);
        }
    }
    float* Yn = Y + (size_t)n * 2304;
    #pragma unroll
    for (int nt = 0; nt < 3; nt++) {
        int r3 = mt2 * 16 + lr;
        int r2 = nh * 24 + nt * 8 + 2 * lc;
        *(float2*)(Yn + r3 * 48 + r2)       = make_float2(a2[nt][0], a2[nt][1]);
        *(float2*)(Yn + (r3 + 8) * 48 + r2) = make_float2(a2[nt][2], a2[nt][3]);
    }
}

// ---------------------------------------------------------------------------
// Pipelined tf32 TC GEMM:  C[M,N] = A[M,K] (fp32) @ B[N,K]^T (tf32)
// Wait-then-issue double buffering (R7/R10-measured).
// ---------------------------------------------------------------------------
template <int BM, int BN, int BK, int MW, int NW>
__global__ void __launch_bounds__(256) k_gemm_tc_p(
    const float* __restrict__ A, const uint32_t* __restrict__ B,
    float* __restrict__ C, int M, int N, int K)
{
    constexpr int WM = BM / MW, WN = BN / NW;
    constexpr int MT = WM / 16, NT = WN / 8;
    constexpr int LDSS = BK + 4;
    extern __shared__ uint32_t smg[];
    float*    As = (float*)smg;              // 2 x BM x LDSS
    uint32_t* Bs = smg + 2 * BM * LDSS;      // 2 x BN x LDSS

    const int tid  = threadIdx.x;
    const int lane = tid & 31, warp = tid >> 5;
    const int wm = (warp / NW) * WM;
    const int wn = (warp % NW) * WN;
    const int m0 = blockIdx.y * BM;
    const int n0 = blockIdx.x * BN;
    const int lr = lane >> 2, lc = lane & 3;

    const uint32_t as_base = (uint32_t)__cvta_generic_to_shared(As);
    const uint32_t bs_base = (uint32_t)__cvta_generic_to_shared(Bs);

    auto load_stage = [&](int it, int buf) {
        const int k0 = it * BK;
        #pragma unroll
        for (int i = tid; i < BM * BK / 4; i += 256) {
            int r = i / (BK / 4), s = (i % (BK / 4)) * 4;
            cp_async16(as_base + (buf * BM * LDSS + r * LDSS + s) * 4,
                       A + (size_t)(m0 + r) * K + k0 + s);
        }
        #pragma unroll
        for (int i = tid; i < BN * BK / 4; i += 256) {
            int r = i / (BK / 4), s = (i % (BK / 4)) * 4;
            cp_async16(bs_base + (buf * BN * LDSS + r * LDSS + s) * 4,
                       B + (size_t)(n0 + r) * K + k0 + s);
        }
        asm volatile("cp.async.commit_group;");
    };

    float acc[MT][NT][4];
    #pragma unroll
    for (int i = 0; i < MT; i++)
        #pragma unroll
        for (int j = 0; j < NT; j++)
            #pragma unroll
            for (int d = 0; d < 4; d++) acc[i][j][d] = 0.f;

    load_stage(0, 0);
    const int iters = K / BK;

    for (int it = 0; it < iters; it++) {
        asm volatile("cp.async.wait_group 0;" ::: "memory");
        __syncthreads();
        if (it + 1 < iters) load_stage(it + 1, (it + 1) & 1);
        const float*    Ab = As + (it & 1) * BM * LDSS;
        const uint32_t* Bb = Bs + (it & 1) * BN * LDSS;

        #pragma unroll
        for (int kk = 0; kk < BK; kk += 8) {
            uint32_t af[MT][4], bf[NT][2];
            #pragma unroll
            for (int mt = 0; mt < MT; mt++) {
                const float* pa = Ab + (wm + mt * 16 + lr) * LDSS + kk + lc;
                af[mt][0] = cvt_tf32(pa[0]);
                af[mt][1] = cvt_tf32(pa[8 * LDSS]);
                af[mt][2] = cvt_tf32(pa[4]);
                af[mt][3] = cvt_tf32(pa[8 * LDSS + 4]);
            }
            #pragma unroll
            for (int nt = 0; nt < NT; nt++) {
                const uint32_t* pb = Bb + (wn + nt * 8 + lr) * LDSS + kk + lc;
                bf[nt][0] = pb[0];
                bf[nt][1] = pb[4];
            }
            #pragma unroll
            for (int mt = 0; mt < MT; mt++)
                #pragma unroll
                for (int nt = 0; nt < NT; nt++)
                    mma_tf32(acc[mt][nt], af[mt], bf[nt]);
        }
        __syncthreads();
    }

    #pragma unroll
    for (int mt = 0; mt < MT; mt++) {
        int r0 = m0 + wm + mt * 16 + lr;
        #pragma unroll
        for (int nt = 0; nt < NT; nt++) {
            int c0 = n0 + wn + nt * 8 + 2 * lc;
            *(float2*)(C + (size_t)r0 * N + c0)       = make_float2(acc[mt][nt][0], acc[mt][nt][1]);
            *(float2*)(C + (size_t)(r0 + 8) * N + c0) = make_float2(acc[mt][nt][2], acc[mt][nt][3]);
        }
    }
}

#define GEMMA_SMEM ((2*64*68 + 2*32*68) * 4)
#define GEMMS_SMEM ((2*128*68 + 2*64*68) * 4)

// ---------------------------------------------------------------------------
// Row softmax for A (2048 x 256): warp-per-row, shfl-only.
// ---------------------------------------------------------------------------
__global__ void __launch_bounds__(256) k_softmaxA(
    const float* __restrict__ A, float* __restrict__ out)
{
    const int w = threadIdx.x >> 5, lane = threadIdx.x & 31;
    const int n = blockIdx.x * 8 + w;
    const float4* a4 = (const float4*)(A + (size_t)n * 256);
    float4 v0 = a4[lane];
    float4 v1 = a4[lane + 32];

    float m = fmaxf(fmaxf(fmaxf(v0.x, v0.y), fmaxf(v0.z, v0.w)),
                    fmaxf(fmaxf(v1.x, v1.y), fmaxf(v1.z, v1.w)));
    #pragma unroll
    for (int o = 16; o > 0; o >>= 1) m = fmaxf(m, __shfl_xor_sync(0xffffffffu, m, o));

    float e0 = __expf(v0.x - m), e1 = __expf(v0.y - m);
    float e2 = __expf(v0.z - m), e3 = __expf(v0.w - m);
    float e4 = __expf(v1.x - m), e5 = __expf(v1.y - m);
    float e6 = __expf(v1.z - m), e7 = __expf(v1.w - m);
    float s = ((e0 + e1) + (e2 + e3)) + ((e4 + e5) + (e6 + e7));
    #pragma unroll
    for (int o = 16; o > 0; o >>= 1) s += __shfl_xor_sync(0xffffffffu, s, o);
    float inv = 1.f / s;

    float4* o4 = (float4*)(out + (size_t)n * 256);
    o4[lane]      = make_float4(e0 * inv, e1 * inv, e2 * inv, e3 * inv);
    o4[lane + 32] = make_float4(e4 * inv, e5 * inv, e6 * inv, e7 * inv);
}

// ---------------------------------------------------------------------------
// Fused decode: one CTA per sample n, 192 threads = 6 warps, 3 CTAs/SM.
// (R10-measured: stride-48 XOR swizzle, St/Bsm aliased, register-lean stage2.)
// ---------------------------------------------------------------------------
#define DEC_SMEM_U32 (192*48 + 192*48)
__global__ void __launch_bounds__(192, 3) k_dec(
    const float* __restrict__ S, const uint32_t* __restrict__ smB,
    const uint32_t* __restrict__ smC, float* __restrict__ out)
{
    extern __shared__ uint32_t smd[];
    uint32_t* Cs = smd;              // smC [k][r3] swizzled; then Ua [k][r2]
    uint32_t* R2 = smd + 192 * 48;   // St (48x48) then Bsm (192x48), swizzled

    const int n = blockIdx.x, tid = threadIdx.x;
    const int w = tid >> 5, lane = tid & 31;
    const int lr = lane >> 2, lc = lane & 3;
    const int sw = (lr & 6) << 1;

    for (int i = tid; i < 2304; i += 192) {
        int r = i / 12, c = (i % 12) * 4;
        uint4 v = *(const uint4*)(smC + r * 48 + c);
        uint32_t* p = &Cs[r * 48 + (c ^ ((r & 6) << 1))];
        p[0] = v.x; p[1] = v.y; p[2] = v.z; p[3] = v.w;
    }
    const float* Sn = S + (size_t)n * 2304;
    for (int i = tid; i < 576; i += 192) {
        int r3 = i / 12, r2 = (i % 12) * 4;
        float4 v = *(const float4*)(Sn + r3 * 48 + r2);
        R2[(r2 + 0) * 48 + (r3 ^ (((r2 + 0) & 6) << 1))] = cvt_tf32(v.x);
        R2[(r2 + 1) * 48 + (r3 ^ (((r2 + 1) & 6) << 1))] = cvt_tf32(v.y);
        R2[(r2 + 2) * 48 + (r3 ^ (((r2 + 2) & 6) << 1))] = cvt_tf32(v.z);
        R2[(r2 + 3) * 48 + (r3 ^ (((r2 + 3) & 6) << 1))] = cvt_tf32(v.w);
    }
    __syncthreads();

    float a1[2][6][4];
    #pragma unroll
    for (int i = 0; i < 2; i++)
        #pragma unroll
        for (int j = 0; j < 6; j++)
            #pragma unroll
            for (int d = 0; d < 4; d++) a1[i][j][d] = 0.f;

    #pragma unroll
    for (int kk = 0; kk < 48; kk += 8) {
        const int c0 = (kk ^ sw) + lc;
        const int c1 = ((kk + 4) ^ sw) + lc;
        uint32_t af[2][4], bf[6][2];
        #pragma unroll
        for (int mt = 0; mt < 2; mt++) {
            const uint32_t* pa = &Cs[(w * 32 + mt * 16 + lr) * 48];
            af[mt][0] = pa[c0]; af[mt][1] = pa[384 + c0];
            af[mt][2] = pa[c1]; af[mt][3] = pa[384 + c1];
        }
        #pragma unroll
        for (int nt = 0; nt < 6; nt++) {
            const uint32_t* pb = &R2[(nt * 8 + lr) * 48];
            bf[nt][0] = pb[c0]; bf[nt][1] = pb[c1];
        }
        #pragma unroll
        for (int mt = 0; mt < 2; mt++)
            #pragma unroll
            for (int nt = 0; nt < 6; nt++)
                mma_tf32(a1[mt][nt], af[mt], bf[nt]);
    }
    __syncthreads();

    #pragma unroll
    for (int mt = 0; mt < 2; mt++) {
        int k0 = w * 32 + mt * 16 + lr;
        #pragma unroll
        for (int nt = 0; nt < 6; nt++) {
            int cc = ((nt * 8 + 2 * lc) ^ sw);
            Cs[k0 * 48 + cc]           = cvt_tf32(a1[mt][nt][0]);
            Cs[k0 * 48 + cc + 1]       = cvt_tf32(a1[mt][nt][1]);
            Cs[(k0 + 8) * 48 + cc]     = cvt_tf32(a1[mt][nt][2]);
            Cs[(k0 + 8) * 48 + cc + 1] = cvt_tf32(a1[mt][nt][3]);
        }
    }
    for (int i = tid; i < 2304; i += 192) {
        int r = i / 12, c = (i % 12) * 4;
        uint4 v = *(const uint4*)(smB + r * 48 + c);
        uint32_t* p = &R2[r * 48 + (c ^ ((r & 6) << 1))];
        p[0] = v.x; p[1] = v.y; p[2] = v.z; p[3] = v.w;
    }
    __syncthreads();

    float* on = out + (size_t)n * 36864;
    const int wm = (w % 3) * 64;
    const int nb = (w / 3) * 24;
    #pragma unroll 1
    for (int np = 0; np < 4; np++) {
        const int wn = nb + np * 48;
        #pragma unroll 1
        for (int mp = 0; mp < 2; mp++) {
            const int mbase = wm + mp * 32;
            float a2[2][3][4];
            #pragma unroll
            for (int i = 0; i < 2; i++)
                #pragma unroll
                for (int j = 0; j < 3; j++)
                    #pragma unroll
                    for (int d = 0; d < 4; d++) a2[i][j][d] = 0.f;

            #pragma unroll
            for (int kk = 0; kk < 48; kk += 8) {
                const int c0 = (kk ^ sw) + lc;
                const int c1 = ((kk + 4) ^ sw) + lc;
                uint32_t af[2][4], bf[3][2];
                #pragma unroll
                for (int mt = 0; mt < 2; mt++) {
                    const uint32_t* pa = &Cs[(mbase + mt * 16 + lr) * 48];
                    af[mt][0] = pa[c0]; af[mt][1] = pa[384 + c0];
                    af[mt][2] = pa[c1]; af[mt][3] = pa[384 + c1];
                }
                #pragma unroll
                for (int nt = 0; nt < 3; nt++) {
                    const uint32_t* pb = &R2[(wn + nt * 8 + lr) * 48];
                    bf[nt][0] = pb[c0]; bf[nt][1] = pb[c1];
                }
                #pragma unroll
                for (int mt = 0; mt < 2; mt++)
                    #pragma unroll
                    for (int nt = 0; nt < 3; nt++)
                        mma_tf32(a2[mt][nt], af[mt], bf[nt]);
            }
            #pragma unroll
            for (int mt = 0; mt < 2; mt++) {
                int row = mbase + mt * 16 + lr;
                #pragma unroll
                for (int nt = 0; nt < 3; nt++) {
                    int col = wn + nt * 8 + 2 * lc;
                    *(float2*)(on + (size_t)row * 192 + col) =
                        make_float2(a2[mt][nt][0], a2[mt][nt][1]);
                    *(float2*)(on + (size_t)(row + 8) * 192 + col) =
                        make_float2(a2[mt][nt][2], a2[mt][nt][3]);
                }
            }
        }
    }
}

// ---------------------------------------------------------------------------
// Launch pipeline (default stream -> sequential; graph-capturable)
// ---------------------------------------------------------------------------
extern "C" void kernel_launch(void* const* d_in, const int* in_sizes, int n_in,
                              void* d_out, int out_size)
{
    const float* X     = (const float*)d_in[0];
    const float* B     = (const float*)d_in[1];
    const float* C     = (const float*)d_in[2];
    const float* G     = (const float*)d_in[3];
    const float* B_inv = (const float*)d_in[4];
    const float* C_inv = (const float*)d_in[5];
    const float* G_inv = (const float*)d_in[6];
    float* out = (float*)d_out;

    float *pBuf2, *pA, *pSmA;
    uint32_t *pSmBT, *pSmCT, *pGt, *pGrt;
    cudaGetSymbolAddress((void**)&pBuf2, g_buf2);
    cudaGetSymbolAddress((void**)&pA,    g_Amat);
    cudaGetSymbolAddress((void**)&pSmA,  g_smA);
    cudaGetSymbolAddress((void**)&pSmBT, g_smBT);
    cudaGetSymbolAddress((void**)&pSmCT, g_smCT);
    cudaGetSymbolAddress((void**)&pGt,   g_Gt);
    cudaGetSymbolAddress((void**)&pGrt,  g_Grt);

    cudaFuncSetAttribute(k_enc, cudaFuncAttributeMaxDynamicSharedMemorySize, ENC_SMEM_U32 * 4);
    cudaFuncSetAttribute(k_dec, cudaFuncAttributeMaxDynamicSharedMemorySize, DEC_SMEM_U32 * 4);
    cudaFuncSetAttribute((const void*)k_gemm_tc_p<64, 32, 64, 4, 2>,
                         cudaFuncAttributeMaxDynamicSharedMemorySize, GEMMA_SMEM);
    cudaFuncSetAttribute((const void*)k_gemm_tc_p<128, 64, 64, 4, 2>,
                         cudaFuncAttributeMaxDynamicSharedMemorySize, GEMMS_SMEM);

    // encode + prep in one launch
    k_enc<<<PREP_BLOCKS + NSAMP, 192, ENC_SMEM_U32 * 4>>>(
        X, B_inv, C_inv, pBuf2, G_inv, G, B, C, pGt, pGrt, pSmBT, pSmCT);

    // A = Y(2048x2304) @ G_inv(2304x256); softmax rows
    k_gemm_tc_p<64, 32, 64, 4, 2><<<dim3(8, 32), 256, GEMMA_SMEM>>>(
        pBuf2, pGt, pA, 2048, 256, 2304);
    k_softmaxA<<<256, 256>>>(pA, pSmA);

    // S = smA(2048x256) @ relu(G)(256x2304) — BK=64: 4 k-iters, fewer barriers
    k_gemm_tc_p<128, 64, 64, 4, 2><<<dim3(36, 16), 256, GEMMS_SMEM>>>(
        pSmA, pGrt, pBuf2, 2048, 2304, 256);

    // decode: out[n] = (smC @ S[n]) @ smB^T
    k_dec<<<2048, 192, DEC_SMEM_U32 * 4>>>(pBuf2, pSmBT, pSmCT, out);
}

// round 14
// speedup vs baseline: 1.0337x; 1.0122x over previous
#include <cuda_runtime.h>
#include <cstdint>
#include <cstddef>

// Problem dims (fixed)
#define NSAMP 2048
#define JDIM  192
#define KDIM  192
#define R1D   256
#define R2D   48
#define R3D   48

#define PREP_BLOCKS 1154   // 576 Gt-transpose + 576 Grt-transpose + 2 softmax

// ---------------------------------------------------------------------------
// Scratch (__device__ globals; no allocation)
// ---------------------------------------------------------------------------
__device__ __align__(16) float    g_buf2[(size_t)NSAMP * R2D * R3D];    // Y(tf32 bits) then S(fp32)
__device__ __align__(16) float    g_Amat[(size_t)NSAMP * R1D];
__device__ __align__(16) uint32_t g_smA [(size_t)NSAMP * R1D];          // tf32 softmax(A)
__device__ __align__(16) uint32_t g_smBT [JDIM * R2D];     // tf32 softmax(B) (192x48)
__device__ __align__(16) uint32_t g_smCT [KDIM * R3D];     // tf32 softmax(C) (192x48)
__device__ __align__(16) uint32_t g_Gt   [R1D * 2304];     // tf32 G_inv^T (256x2304)
__device__ __align__(16) uint32_t g_Grt  [2304 * R1D];     // tf32 relu(G)^T (2304x256)

// ---------------------------------------------------------------------------
// tf32 helpers
// ---------------------------------------------------------------------------
__device__ __forceinline__ uint32_t cvt_tf32(float x) {
    uint32_t r;
    asm("cvt.rna.tf32.f32 %0, %1;" : "=r"(r) : "f"(x));
    return r;
}

__device__ __forceinline__ void mma_tf32(float* d, const uint32_t* a, const uint32_t* b) {
    asm volatile(
        "mma.sync.aligned.m16n8k8.row.col.f32.tf32.tf32.f32 "
        "{%0,%1,%2,%3},{%4,%5,%6,%7},{%8,%9},{%0,%1,%2,%3};"
        : "+f"(d[0]), "+f"(d[1]), "+f"(d[2]), "+f"(d[3])
        : "r"(a[0]), "r"(a[1]), "r"(a[2]), "r"(a[3]), "r"(b[0]), "r"(b[1]));
}

__device__ __forceinline__ void cp_async16(uint32_t smem_dst, const void* gsrc) {
    asm volatile("cp.async.cg.shared.global [%0], [%1], 16;" :: "r"(smem_dst), "l"(gsrc));
}

// ---------------------------------------------------------------------------
// Fused encode + prep: grid = PREP_BLOCKS + 2048, 192 threads, 3 CTAs/SM.
// Y is emitted as tf32 bits (consumed only by gemmA with ATF=true).
// ---------------------------------------------------------------------------
#define ENC_SMEM_U32 (48*196 + 48*196)
__global__ void __launch_bounds__(192, 3) k_enc(
    const float* __restrict__ X, const float* __restrict__ Binv,
    const float* __restrict__ Cinv, uint32_t* __restrict__ Y,
    const float* __restrict__ Gi, const float* __restrict__ G,
    const float* __restrict__ Bm, const float* __restrict__ Cm,
    uint32_t* __restrict__ Gt, uint32_t* __restrict__ Grt,
    uint32_t* __restrict__ smBT, uint32_t* __restrict__ smCT)
{
    extern __shared__ uint32_t sme[];
    const int tid = threadIdx.x;

    // ---------------- prep branch ----------------
    if (blockIdx.x < PREP_BLOCKS) {
        int b = blockIdx.x;
        float* tile = (float*)sme;   // 32x33 floats
        if (b < 576) {
            int br = b >> 3, bc = b & 7;
            for (int i = tid; i < 1024; i += 192) {
                int r = i >> 5, c = i & 31;
                tile[r * 33 + c] = Gi[(size_t)(br * 32 + r) * 256 + bc * 32 + c];
            }
            __syncthreads();
            for (int i = tid; i < 1024; i += 192) {
                int r = i >> 5, c = i & 31;
                Gt[(size_t)(bc * 32 + r) * 2304 + br * 32 + c] = cvt_tf32(tile[c * 33 + r]);
            }
        } else if (b < 1152) {
            int b2 = b - 576;
            int br = b2 & 7, bc = b2 >> 3;
            for (int i = tid; i < 1024; i += 192) {
                int r = i >> 5, c = i & 31;
                tile[r * 33 + c] = G[(size_t)(br * 32 + r) * 2304 + bc * 32 + c];
            }
            __syncthreads();
            for (int i = tid; i < 1024; i += 192) {
                int r = i >> 5, c = i & 31;
                Grt[(size_t)(bc * 32 + r) * 256 + br * 32 + c] =
                    cvt_tf32(fmaxf(tile[c * 33 + r], 0.f));
            }
        } else {
            const float* in = (b == 1152) ? Bm : Cm;
            uint32_t* outp = (b == 1152) ? smBT : smCT;
            const float* p = in + tid * 48;
            float m = -1e30f;
            #pragma unroll
            for (int j = 0; j < 48; j++) m = fmaxf(m, p[j]);
            float s = 0.f;
            #pragma unroll
            for (int j = 0; j < 48; j++) s += __expf(p[j] - m);
            float inv = 1.f / s;
            #pragma unroll
            for (int j = 0; j < 48; j++)
                outp[tid * 48 + j] = cvt_tf32(__expf(p[j] - m) * inv);
        }
        return;
    }

    // ---------------- encode branch ----------------
    uint32_t* Fs = sme;                     // 48*196 tf32: Binv, later Cinv
    float*    Xf = (float*)(sme + 48*196);  // 2 x 192 x 20 fp32
    uint32_t* Ts = sme + 48*196;            // later: T^T 48x196 tf32

    const int n = blockIdx.x - PREP_BLOCKS;
    const int w = tid >> 5, lane = tid & 31;
    const int lr = lane >> 2, lc = lane & 3;

    for (int i = tid; i < 2304; i += 192) {
        int r = i / 48, c = (i % 48) * 4;
        float4 v = *(const float4*)(Binv + r * 192 + c);
        uint32_t* p = &Fs[r * 196 + c];
        p[0] = cvt_tf32(v.x); p[1] = cvt_tf32(v.y);
        p[2] = cvt_tf32(v.z); p[3] = cvt_tf32(v.w);
    }

    const uint32_t xs_base = (uint32_t)__cvta_generic_to_shared(Xf);
    const float* Xn = X + (size_t)n * 36864;

    auto load_chunk = [&](int ck, int buf) {
        const float* src = Xn + ck * 16;
        #pragma unroll
        for (int i = tid; i < 768; i += 192) {
            int row = i >> 2, seg = i & 3;
            cp_async16(xs_base + (buf * 3840 + row * 20 + seg * 4) * 4,
                       src + row * 192 + seg * 4);
        }
        asm volatile("cp.async.commit_group;");
    };

    load_chunk(0, 0);

    float acc[2][6][4];
    #pragma unroll
    for (int i = 0; i < 2; i++)
        #pragma unroll
        for (int j = 0; j < 6; j++)
            #pragma unroll
            for (int d = 0; d < 4; d++) acc[i][j][d] = 0.f;

    // issue-before-wait (R13-measured win)
    for (int ck = 0; ck < 12; ck++) {
        if (ck < 11) {
            load_chunk(ck + 1, (ck + 1) & 1);
            asm volatile("cp.async.wait_group 1;" ::: "memory");
        } else {
            asm volatile("cp.async.wait_group 0;" ::: "memory");
        }
        __syncthreads();
        const float* Xb = Xf + ((ck & 1) ? 3840 : 0);

        #pragma unroll
        for (int kk = 0; kk < 16; kk += 8) {
            uint32_t af[2][4], bf[6][2];
            #pragma unroll
            for (int mt = 0; mt < 2; mt++) {
                const float* pa = Xb + (w * 32 + mt * 16 + lr) * 20 + kk + lc;
                af[mt][0] = cvt_tf32(pa[0]);
                af[mt][1] = cvt_tf32(pa[160]);
                af[mt][2] = cvt_tf32(pa[4]);
                af[mt][3] = cvt_tf32(pa[164]);
            }
            #pragma unroll
            for (int nt = 0; nt < 6; nt++) {
                const uint32_t* pb = &Fs[(nt * 8 + lr) * 196 + ck * 16 + kk + lc];
                bf[nt][0] = pb[0]; bf[nt][1] = pb[4];
            }
            #pragma unroll
            for (int mt = 0; mt < 2; mt++)
                #pragma unroll
                for (int nt = 0; nt < 6; nt++)
                    mma_tf32(acc[mt][nt], af[mt], bf[nt]);
        }
        __syncthreads();
    }

    #pragma unroll
    for (int mt = 0; mt < 2; mt++) {
        int k0 = w * 32 + mt * 16 + lr;
        #pragma unroll
        for (int nt = 0; nt < 6; nt++) {
            int r2 = nt * 8 + 2 * lc;
            Ts[r2 * 196 + k0]           = cvt_tf32(acc[mt][nt][0]);
            Ts[(r2 + 1) * 196 + k0]     = cvt_tf32(acc[mt][nt][1]);
            Ts[r2 * 196 + k0 + 8]       = cvt_tf32(acc[mt][nt][2]);
            Ts[(r2 + 1) * 196 + k0 + 8] = cvt_tf32(acc[mt][nt][3]);
        }
    }
    for (int i = tid; i < 2304; i += 192) {
        int r = i / 48, c = (i % 48) * 4;
        float4 v = *(const float4*)(Cinv + r * 192 + c);
        uint32_t* p = &Fs[r * 196 + c];
        p[0] = cvt_tf32(v.x); p[1] = cvt_tf32(v.y);
        p[2] = cvt_tf32(v.z); p[3] = cvt_tf32(v.w);
    }
    __syncthreads();

    const int mt2 = w % 3, nh = w / 3;
    float a2[3][4];
    #pragma unroll
    for (int i = 0; i < 3; i++)
        #pragma unroll
        for (int d = 0; d < 4; d++) a2[i][d] = 0.f;

    #pragma unroll 8
    for (int kk = 0; kk < 192; kk += 8) {
        uint32_t af[4];
        const uint32_t* pa = &Fs[(mt2 * 16 + lr) * 196 + kk + lc];
        af[0] = pa[0]; af[1] = pa[1568]; af[2] = pa[4]; af[3] = pa[1572];
        #pragma unroll
        for (int nt = 0; nt < 3; nt++) {
            const uint32_t* pb = &Ts[(nh * 24 + nt * 8 + lr) * 196 + kk + lc];
            uint32_t bf[2] = { pb[0], pb[4] };
            mma_tf32(a2[nt], af, bf);
        }
    }
    // Y emitted as tf32 bits (gemmA consumes with ATF=true)
    uint32_t* Yn = Y + (size_t)n * 2304;
    #pragma unroll
    for (int nt = 0; nt < 3; nt++) {
        int r3 = mt2 * 16 + lr;
        int r2 = nh * 24 + nt * 8 + 2 * lc;
        Yn[r3 * 48 + r2]           = cvt_tf32(a2[nt][0]);
        Yn[r3 * 48 + r2 + 1]       = cvt_tf32(a2[nt][1]);
        Yn[(r3 + 8) * 48 + r2]     = cvt_tf32(a2[nt][2]);
        Yn[(r3 + 8) * 48 + r2 + 1] = cvt_tf32(a2[nt][3]);
    }
}

// ---------------------------------------------------------------------------
// Pipelined tf32 TC GEMM:  C[M,N] = A[M,K] @ B[N,K]^T
// ATF: A is pre-converted tf32 bits (no cvt in the inner loop).
// Issue-before-wait double buffering.
// ---------------------------------------------------------------------------
template <int BM, int BN, int BK, int MW, int NW, bool ATF>
__global__ void __launch_bounds__(256) k_gemm_tc_p(
    const void* __restrict__ Av, const uint32_t* __restrict__ B,
    float* __restrict__ C, int M, int N, int K)
{
    constexpr int WM = BM / MW, WN = BN / NW;
    constexpr int MT = WM / 16, NT = WN / 8;
    constexpr int LDSS = BK + 4;
    extern __shared__ uint32_t smg[];
    uint32_t* As = smg;                      // 2 x BM x LDSS (fp32 or tf32 bits)
    uint32_t* Bs = smg + 2 * BM * LDSS;      // 2 x BN x LDSS

    const float* A = (const float*)Av;       // 4-byte elements either way

    const int tid  = threadIdx.x;
    const int lane = tid & 31, warp = tid >> 5;
    const int wm = (warp / NW) * WM;
    const int wn = (warp % NW) * WN;
    const int m0 = blockIdx.y * BM;
    const int n0 = blockIdx.x * BN;
    const int lr = lane >> 2, lc = lane & 3;

    const uint32_t as_base = (uint32_t)__cvta_generic_to_shared(As);
    const uint32_t bs_base = (uint32_t)__cvta_generic_to_shared(Bs);

    auto load_stage = [&](int it, int buf) {
        const int k0 = it * BK;
        #pragma unroll
        for (int i = tid; i < BM * BK / 4; i += 256) {
            int r = i / (BK / 4), s = (i % (BK / 4)) * 4;
            cp_async16(as_base + (buf * BM * LDSS + r * LDSS + s) * 4,
                       A + (size_t)(m0 + r) * K + k0 + s);
        }
        #pragma unroll
        for (int i = tid; i < BN * BK / 4; i += 256) {
            int r = i / (BK / 4), s = (i % (BK / 4)) * 4;
            cp_async16(bs_base + (buf * BN * LDSS + r * LDSS + s) * 4,
                       B + (size_t)(n0 + r) * K + k0 + s);
        }
        asm volatile("cp.async.commit_group;");
    };

    float acc[MT][NT][4];
    #pragma unroll
    for (int i = 0; i < MT; i++)
        #pragma unroll
        for (int j = 0; j < NT; j++)
            #pragma unroll
            for (int d = 0; d < 4; d++) acc[i][j][d] = 0.f;

    load_stage(0, 0);
    const int iters = K / BK;

    for (int it = 0; it < iters; it++) {
        if (it + 1 < iters) {
            load_stage(it + 1, (it + 1) & 1);
            asm volatile("cp.async.wait_group 1;" ::: "memory");
        } else {
            asm volatile("cp.async.wait_group 0;" ::: "memory");
        }
        __syncthreads();
        const uint32_t* Ab = As + (it & 1) * BM * LDSS;
        const uint32_t* Bb = Bs + (it & 1) * BN * LDSS;

        #pragma unroll
        for (int kk = 0; kk < BK; kk += 8) {
            uint32_t af[MT][4], bf[NT][2];
            #pragma unroll
            for (int mt = 0; mt < MT; mt++) {
                const uint32_t* pa = Ab + (wm + mt * 16 + lr) * LDSS + kk + lc;
                if (ATF) {
                    af[mt][0] = pa[0];
                    af[mt][1] = pa[8 * LDSS];
                    af[mt][2] = pa[4];
                    af[mt][3] = pa[8 * LDSS + 4];
                } else {
                    af[mt][0] = cvt_tf32(__uint_as_float(pa[0]));
                    af[mt][1] = cvt_tf32(__uint_as_float(pa[8 * LDSS]));
                    af[mt][2] = cvt_tf32(__uint_as_float(pa[4]));
                    af[mt][3] = cvt_tf32(__uint_as_float(pa[8 * LDSS + 4]));
                }
            }
            #pragma unroll
            for (int nt = 0; nt < NT; nt++) {
                const uint32_t* pb = Bb + (wn + nt * 8 + lr) * LDSS + kk + lc;
                bf[nt][0] = pb[0];
                bf[nt][1] = pb[4];
            }
            #pragma unroll
            for (int mt = 0; mt < MT; mt++)
                #pragma unroll
                for (int nt = 0; nt < NT; nt++)
                    mma_tf32(acc[mt][nt], af[mt], bf[nt]);
        }
        __syncthreads();
    }

    #pragma unroll
    for (int mt = 0; mt < MT; mt++) {
        int r0 = m0 + wm + mt * 16 + lr;
        #pragma unroll
        for (int nt = 0; nt < NT; nt++) {
            int c0 = n0 + wn + nt * 8 + 2 * lc;
            *(float2*)(C + (size_t)r0 * N + c0)       = make_float2(acc[mt][nt][0], acc[mt][nt][1]);
            *(float2*)(C + (size_t)(r0 + 8) * N + c0) = make_float2(acc[mt][nt][2], acc[mt][nt][3]);
        }
    }
}

#define GEMMA_SMEM ((2*64*68 + 2*32*68) * 4)
#define GEMMS_SMEM ((2*128*36 + 2*64*36) * 4)

// ---------------------------------------------------------------------------
// Row softmax for A (2048 x 256): warp-per-row, shfl-only; output tf32 bits.
// ---------------------------------------------------------------------------
__global__ void __launch_bounds__(256) k_softmaxA(
    const float* __restrict__ A, uint32_t* __restrict__ out)
{
    const int w = threadIdx.x >> 5, lane = threadIdx.x & 31;
    const int n = blockIdx.x * 8 + w;
    const float4* a4 = (const float4*)(A + (size_t)n * 256);
    float4 v0 = a4[lane];
    float4 v1 = a4[lane + 32];

    float m = fmaxf(fmaxf(fmaxf(v0.x, v0.y), fmaxf(v0.z, v0.w)),
                    fmaxf(fmaxf(v1.x, v1.y), fmaxf(v1.z, v1.w)));
    #pragma unroll
    for (int o = 16; o > 0; o >>= 1) m = fmaxf(m, __shfl_xor_sync(0xffffffffu, m, o));

    float e0 = __expf(v0.x - m), e1 = __expf(v0.y - m);
    float e2 = __expf(v0.z - m), e3 = __expf(v0.w - m);
    float e4 = __expf(v1.x - m), e5 = __expf(v1.y - m);
    float e6 = __expf(v1.z - m), e7 = __expf(v1.w - m);
    float s = ((e0 + e1) + (e2 + e3)) + ((e4 + e5) + (e6 + e7));
    #pragma unroll
    for (int o = 16; o > 0; o >>= 1) s += __shfl_xor_sync(0xffffffffu, s, o);
    float inv = 1.f / s;

    uint4* o4 = (uint4*)(out + (size_t)n * 256);
    o4[lane]      = make_uint4(cvt_tf32(e0 * inv), cvt_tf32(e1 * inv),
                               cvt_tf32(e2 * inv), cvt_tf32(e3 * inv));
    o4[lane + 32] = make_uint4(cvt_tf32(e4 * inv), cvt_tf32(e5 * inv),
                               cvt_tf32(e6 * inv), cvt_tf32(e7 * inv));
}

// ---------------------------------------------------------------------------
// Fused decode: one CTA per sample n, 192 threads = 6 warps, 3 CTAs/SM.
// (R10-measured: stride-48 XOR swizzle, St/Bsm aliased, register-lean stage2.)
// ---------------------------------------------------------------------------
#define DEC_SMEM_U32 (192*48 + 192*48)
__global__ void __launch_bounds__(192, 3) k_dec(
    const float* __restrict__ S, const uint32_t* __restrict__ smB,
    const uint32_t* __restrict__ smC, float* __restrict__ out)
{
    extern __shared__ uint32_t smd[];
    uint32_t* Cs = smd;              // smC [k][r3] swizzled; then Ua [k][r2]
    uint32_t* R2 = smd + 192 * 48;   // St (48x48) then Bsm (192x48), swizzled

    const int n = blockIdx.x, tid = threadIdx.x;
    const int w = tid >> 5, lane = tid & 31;
    const int lr = lane >> 2, lc = lane & 3;
    const int sw = (lr & 6) << 1;

    for (int i = tid; i < 2304; i += 192) {
        int r = i / 12, c = (i % 12) * 4;
        uint4 v = *(const uint4*)(smC + r * 48 + c);
        uint32_t* p = &Cs[r * 48 + (c ^ ((r & 6) << 1))];
        p[0] = v.x; p[1] = v.y; p[2] = v.z; p[3] = v.w;
    }
    const float* Sn = S + (size_t)n * 2304;
    for (int i = tid; i < 576; i += 192) {
        int r3 = i / 12, r2 = (i % 12) * 4;
        float4 v = *(const float4*)(Sn + r3 * 48 + r2);
        R2[(r2 + 0) * 48 + (r3 ^ (((r2 + 0) & 6) << 1))] = cvt_tf32(v.x);
        R2[(r2 + 1) * 48 + (r3 ^ (((r2 + 1) & 6) << 1))] = cvt_tf32(v.y);
        R2[(r2 + 2) * 48 + (r3 ^ (((r2 + 2) & 6) << 1))] = cvt_tf32(v.z);
        R2[(r2 + 3) * 48 + (r3 ^ (((r2 + 3) & 6) << 1))] = cvt_tf32(v.w);
    }
    __syncthreads();

    float a1[2][6][4];
    #pragma unroll
    for (int i = 0; i < 2; i++)
        #pragma unroll
        for (int j = 0; j < 6; j++)
            #pragma unroll
            for (int d = 0; d < 4; d++) a1[i][j][d] = 0.f;

    #pragma unroll
    for (int kk = 0; kk < 48; kk += 8) {
        const int c0 = (kk ^ sw) + lc;
        const int c1 = ((kk + 4) ^ sw) + lc;
        uint32_t af[2][4], bf[6][2];
        #pragma unroll
        for (int mt = 0; mt < 2; mt++) {
            const uint32_t* pa = &Cs[(w * 32 + mt * 16 + lr) * 48];
            af[mt][0] = pa[c0]; af[mt][1] = pa[384 + c0];
            af[mt][2] = pa[c1]; af[mt][3] = pa[384 + c1];
        }
        #pragma unroll
        for (int nt = 0; nt < 6; nt++) {
            const uint32_t* pb = &R2[(nt * 8 + lr) * 48];
            bf[nt][0] = pb[c0]; bf[nt][1] = pb[c1];
        }
        #pragma unroll
        for (int mt = 0; mt < 2; mt++)
            #pragma unroll
            for (int nt = 0; nt < 6; nt++)
                mma_tf32(a1[mt][nt], af[mt], bf[nt]);
    }
    __syncthreads();

    #pragma unroll
    for (int mt = 0; mt < 2; mt++) {
        int k0 = w * 32 + mt * 16 + lr;
        #pragma unroll
        for (int nt = 0; nt < 6; nt++) {
            int cc = ((nt * 8 + 2 * lc) ^ sw);
            Cs[k0 * 48 + cc]           = cvt_tf32(a1[mt][nt][0]);
            Cs[k0 * 48 + cc + 1]       = cvt_tf32(a1[mt][nt][1]);
            Cs[(k0 + 8) * 48 + cc]     = cvt_tf32(a1[mt][nt][2]);
            Cs[(k0 + 8) * 48 + cc + 1] = cvt_tf32(a1[mt][nt][3]);
        }
    }
    for (int i = tid; i < 2304; i += 192) {
        int r = i / 12, c = (i % 12) * 4;
        uint4 v = *(const uint4*)(smB + r * 48 + c);
        uint32_t* p = &R2[r * 48 + (c ^ ((r & 6) << 1))];
        p[0] = v.x; p[1] = v.y; p[2] = v.z; p[3] = v.w;
    }
    __syncthreads();

    float* on = out + (size_t)n * 36864;
    const int wm = (w % 3) * 64;
    const int nb = (w / 3) * 24;
    #pragma unroll 1
    for (int np = 0; np < 4; np++) {
        const int wn = nb + np * 48;
        #pragma unroll 1
        for (int mp = 0; mp < 2; mp++) {
            const int mbase = wm + mp * 32;
            float a2[2][3][4];
            #pragma unroll
            for (int i = 0; i < 2; i++)
                #pragma unroll
                for (int j = 0; j < 3; j++)
                    #pragma unroll
                    for (int d = 0; d < 4; d++) a2[i][j][d] = 0.f;

            #pragma unroll
            for (int kk = 0; kk < 48; kk += 8) {
                const int c0 = (kk ^ sw) + lc;
                const int c1 = ((kk + 4) ^ sw) + lc;
                uint32_t af[2][4], bf[3][2];
                #pragma unroll
                for (int mt = 0; mt < 2; mt++) {
                    const uint32_t* pa = &Cs[(mbase + mt * 16 + lr) * 48];
                    af[mt][0] = pa[c0]; af[mt][1] = pa[384 + c0];
                    af[mt][2] = pa[c1]; af[mt][3] = pa[384 + c1];
                }
                #pragma unroll
                for (int nt = 0; nt < 3; nt++) {
                    const uint32_t* pb = &R2[(wn + nt * 8 + lr) * 48];
                    bf[nt][0] = pb[c0]; bf[nt][1] = pb[c1];
                }
                #pragma unroll
                for (int mt = 0; mt < 2; mt++)
                    #pragma unroll
                    for (int nt = 0; nt < 3; nt++)
                        mma_tf32(a2[mt][nt], af[mt], bf[nt]);
            }
            #pragma unroll
            for (int mt = 0; mt < 2; mt++) {
                int row = mbase + mt * 16 + lr;
                #pragma unroll
                for (int nt = 0; nt < 3; nt++) {
                    int col = wn + nt * 8 + 2 * lc;
                    *(float2*)(on + (size_t)row * 192 + col) =
                        make_float2(a2[mt][nt][0], a2[mt][nt][1]);
                    *(float2*)(on + (size_t)(row + 8) * 192 + col) =
                        make_float2(a2[mt][nt][2], a2[mt][nt][3]);
                }
            }
        }
    }
}

// ---------------------------------------------------------------------------
// Launch pipeline (default stream -> sequential; graph-capturable)
// ---------------------------------------------------------------------------
extern "C" void kernel_launch(void* const* d_in, const int* in_sizes, int n_in,
                              void* d_out, int out_size)
{
    const float* X     = (const float*)d_in[0];
    const float* B     = (const float*)d_in[1];
    const float* C     = (const float*)d_in[2];
    const float* G     = (const float*)d_in[3];
    const float* B_inv = (const float*)d_in[4];
    const float* C_inv = (const float*)d_in[5];
    const float* G_inv = (const float*)d_in[6];
    float* out = (float*)d_out;

    float *pBuf2, *pA;
    uint32_t *pSmA, *pSmBT, *pSmCT, *pGt, *pGrt;
    cudaGetSymbolAddress((void**)&pBuf2, g_buf2);
    cudaGetSymbolAddress((void**)&pA,    g_Amat);
    cudaGetSymbolAddress((void**)&pSmA,  g_smA);
    cudaGetSymbolAddress((void**)&pSmBT, g_smBT);
    cudaGetSymbolAddress((void**)&pSmCT, g_smCT);
    cudaGetSymbolAddress((void**)&pGt,   g_Gt);
    cudaGetSymbolAddress((void**)&pGrt,  g_Grt);

    cudaFuncSetAttribute(k_enc, cudaFuncAttributeMaxDynamicSharedMemorySize, ENC_SMEM_U32 * 4);
    cudaFuncSetAttribute(k_dec, cudaFuncAttributeMaxDynamicSharedMemorySize, DEC_SMEM_U32 * 4);
    cudaFuncSetAttribute((const void*)k_gemm_tc_p<64, 32, 64, 4, 2, true>,
                         cudaFuncAttributeMaxDynamicSharedMemorySize, GEMMA_SMEM);
    cudaFuncSetAttribute((const void*)k_gemm_tc_p<128, 64, 32, 4, 2, true>,
                         cudaFuncAttributeMaxDynamicSharedMemorySize, GEMMS_SMEM);

    // encode + prep in one launch; Y emitted as tf32 bits into g_buf2
    k_enc<<<PREP_BLOCKS + NSAMP, 192, ENC_SMEM_U32 * 4>>>(
        X, B_inv, C_inv, (uint32_t*)pBuf2, G_inv, G, B, C, pGt, pGrt, pSmBT, pSmCT);

    // A = Y(tf32) @ G_inv^T(tf32); softmax rows (output tf32 bits)
    k_gemm_tc_p<64, 32, 64, 4, 2, true><<<dim3(8, 32), 256, GEMMA_SMEM>>>(
        pBuf2, pGt, pA, 2048, 256, 2304);
    k_softmaxA<<<256, 256>>>(pA, pSmA);

    // S = smA(tf32) @ relu(G)^T(tf32) -> fp32 into g_buf2
    k_gemm_tc_p<128, 64, 32, 4, 2, true><<<dim3(36, 16), 256, GEMMS_SMEM>>>(
        pSmA, pGrt, pBuf2, 2048, 2304, 256);

    // decode: out[n] = (smC @ S[n]) @ smB^T
    k_dec<<<2048, 192, DEC_SMEM_U32 * 4>>>(pBuf2, pSmBT, pSmCT, out);
}

// round 15
// speedup vs baseline: 1.0355x; 1.0017x over previous
#include <cuda_runtime.h>
#include <cstdint>
#include <cstddef>

// Problem dims (fixed)
#define NSAMP 2048
#define JDIM  192
#define KDIM  192
#define R1D   256
#define R2D   48
#define R3D   48

#define PREP_BLOCKS 1154   // 576 Gt-transpose + 576 Grt-transpose + 2 softmax

// ---------------------------------------------------------------------------
// Scratch (__device__ globals; no allocation)
// ---------------------------------------------------------------------------
__device__ __align__(16) float    g_buf2[(size_t)NSAMP * R2D * R3D];    // Y(tf32 bits) then S(fp32)
__device__ __align__(16) float    g_Amat[(size_t)NSAMP * R1D];
__device__ __align__(16) uint32_t g_smA [(size_t)NSAMP * R1D];          // tf32 softmax(A)
__device__ __align__(16) uint32_t g_smBT [JDIM * R2D];     // tf32 softmax(B) (192x48)
__device__ __align__(16) uint32_t g_smCT [KDIM * R3D];     // tf32 softmax(C) (192x48)
__device__ __align__(16) uint32_t g_Gt   [R1D * 2304];     // tf32 G_inv^T (256x2304)
__device__ __align__(16) uint32_t g_Grt  [2304 * R1D];     // tf32 relu(G)^T (2304x256)

// ---------------------------------------------------------------------------
// tf32 helpers
// ---------------------------------------------------------------------------
__device__ __forceinline__ uint32_t cvt_tf32(float x) {
    uint32_t r;
    asm("cvt.rna.tf32.f32 %0, %1;" : "=r"(r) : "f"(x));
    return r;
}

__device__ __forceinline__ void mma_tf32(float* d, const uint32_t* a, const uint32_t* b) {
    asm volatile(
        "mma.sync.aligned.m16n8k8.row.col.f32.tf32.tf32.f32 "
        "{%0,%1,%2,%3},{%4,%5,%6,%7},{%8,%9},{%0,%1,%2,%3};"
        : "+f"(d[0]), "+f"(d[1]), "+f"(d[2]), "+f"(d[3])
        : "r"(a[0]), "r"(a[1]), "r"(a[2]), "r"(a[3]), "r"(b[0]), "r"(b[1]));
}

__device__ __forceinline__ void cp_async16(uint32_t smem_dst, const void* gsrc) {
    asm volatile("cp.async.cg.shared.global [%0], [%1], 16;" :: "r"(smem_dst), "l"(gsrc));
}

// ---------------------------------------------------------------------------
// Fused encode + prep: grid = PREP_BLOCKS + 2048, 192 threads, 3 CTAs/SM.
// Y is emitted as tf32 bits (consumed only by gemmA with ATF=true).
// ---------------------------------------------------------------------------
#define ENC_SMEM_U32 (48*196 + 48*196)
__global__ void __launch_bounds__(192, 3) k_enc(
    const float* __restrict__ X, const float* __restrict__ Binv,
    const float* __restrict__ Cinv, uint32_t* __restrict__ Y,
    const float* __restrict__ Gi, const float* __restrict__ G,
    const float* __restrict__ Bm, const float* __restrict__ Cm,
    uint32_t* __restrict__ Gt, uint32_t* __restrict__ Grt,
    uint32_t* __restrict__ smBT, uint32_t* __restrict__ smCT)
{
    extern __shared__ uint32_t sme[];
    const int tid = threadIdx.x;

    // ---------------- prep branch ----------------
    if (blockIdx.x < PREP_BLOCKS) {
        int b = blockIdx.x;
        float* tile = (float*)sme;   // 32x33 floats
        if (b < 576) {
            int br = b >> 3, bc = b & 7;
            for (int i = tid; i < 1024; i += 192) {
                int r = i >> 5, c = i & 31;
                tile[r * 33 + c] = Gi[(size_t)(br * 32 + r) * 256 + bc * 32 + c];
            }
            __syncthreads();
            for (int i = tid; i < 1024; i += 192) {
                int r = i >> 5, c = i & 31;
                Gt[(size_t)(bc * 32 + r) * 2304 + br * 32 + c] = cvt_tf32(tile[c * 33 + r]);
            }
        } else if (b < 1152) {
            int b2 = b - 576;
            int br = b2 & 7, bc = b2 >> 3;
            for (int i = tid; i < 1024; i += 192) {
                int r = i >> 5, c = i & 31;
                tile[r * 33 + c] = G[(size_t)(br * 32 + r) * 2304 + bc * 32 + c];
            }
            __syncthreads();
            for (int i = tid; i < 1024; i += 192) {
                int r = i >> 5, c = i & 31;
                Grt[(size_t)(bc * 32 + r) * 256 + br * 32 + c] =
                    cvt_tf32(fmaxf(tile[c * 33 + r], 0.f));
            }
        } else {
            const float* in = (b == 1152) ? Bm : Cm;
            uint32_t* outp = (b == 1152) ? smBT : smCT;
            const float* p = in + tid * 48;
            float m = -1e30f;
            #pragma unroll
            for (int j = 0; j < 48; j++) m = fmaxf(m, p[j]);
            float s = 0.f;
            #pragma unroll
            for (int j = 0; j < 48; j++) s += __expf(p[j] - m);
            float inv = 1.f / s;
            #pragma unroll
            for (int j = 0; j < 48; j++)
                outp[tid * 48 + j] = cvt_tf32(__expf(p[j] - m) * inv);
        }
        return;
    }

    // ---------------- encode branch ----------------
    uint32_t* Fs = sme;                     // 48*196 tf32: Binv, later Cinv
    float*    Xf = (float*)(sme + 48*196);  // 2 x 192 x 20 fp32
    uint32_t* Ts = sme + 48*196;            // later: T^T 48x196 tf32

    const int n = blockIdx.x - PREP_BLOCKS;
    const int w = tid >> 5, lane = tid & 31;
    const int lr = lane >> 2, lc = lane & 3;

    for (int i = tid; i < 2304; i += 192) {
        int r = i / 48, c = (i % 48) * 4;
        float4 v = *(const float4*)(Binv + r * 192 + c);
        uint32_t* p = &Fs[r * 196 + c];
        p[0] = cvt_tf32(v.x); p[1] = cvt_tf32(v.y);
        p[2] = cvt_tf32(v.z); p[3] = cvt_tf32(v.w);
    }

    const uint32_t xs_base = (uint32_t)__cvta_generic_to_shared(Xf);
    const float* Xn = X + (size_t)n * 36864;

    auto load_chunk = [&](int ck, int buf) {
        const float* src = Xn + ck * 16;
        #pragma unroll
        for (int i = tid; i < 768; i += 192) {
            int row = i >> 2, seg = i & 3;
            cp_async16(xs_base + (buf * 3840 + row * 20 + seg * 4) * 4,
                       src + row * 192 + seg * 4);
        }
        asm volatile("cp.async.commit_group;");
    };

    load_chunk(0, 0);

    float acc[2][6][4];
    #pragma unroll
    for (int i = 0; i < 2; i++)
        #pragma unroll
        for (int j = 0; j < 6; j++)
            #pragma unroll
            for (int d = 0; d < 4; d++) acc[i][j][d] = 0.f;

    // issue-before-wait (R13-measured win)
    for (int ck = 0; ck < 12; ck++) {
        if (ck < 11) {
            load_chunk(ck + 1, (ck + 1) & 1);
            asm volatile("cp.async.wait_group 1;" ::: "memory");
        } else {
            asm volatile("cp.async.wait_group 0;" ::: "memory");
        }
        __syncthreads();
        const float* Xb = Xf + ((ck & 1) ? 3840 : 0);

        #pragma unroll
        for (int kk = 0; kk < 16; kk += 8) {
            uint32_t af[2][4], bf[6][2];
            #pragma unroll
            for (int mt = 0; mt < 2; mt++) {
                const float* pa = Xb + (w * 32 + mt * 16 + lr) * 20 + kk + lc;
                af[mt][0] = cvt_tf32(pa[0]);
                af[mt][1] = cvt_tf32(pa[160]);
                af[mt][2] = cvt_tf32(pa[4]);
                af[mt][3] = cvt_tf32(pa[164]);
            }
            #pragma unroll
            for (int nt = 0; nt < 6; nt++) {
                const uint32_t* pb = &Fs[(nt * 8 + lr) * 196 + ck * 16 + kk + lc];
                bf[nt][0] = pb[0]; bf[nt][1] = pb[4];
            }
            #pragma unroll
            for (int mt = 0; mt < 2; mt++)
                #pragma unroll
                for (int nt = 0; nt < 6; nt++)
                    mma_tf32(acc[mt][nt], af[mt], bf[nt]);
        }
        __syncthreads();
    }

    #pragma unroll
    for (int mt = 0; mt < 2; mt++) {
        int k0 = w * 32 + mt * 16 + lr;
        #pragma unroll
        for (int nt = 0; nt < 6; nt++) {
            int r2 = nt * 8 + 2 * lc;
            Ts[r2 * 196 + k0]           = cvt_tf32(acc[mt][nt][0]);
            Ts[(r2 + 1) * 196 + k0]     = cvt_tf32(acc[mt][nt][1]);
            Ts[r2 * 196 + k0 + 8]       = cvt_tf32(acc[mt][nt][2]);
            Ts[(r2 + 1) * 196 + k0 + 8] = cvt_tf32(acc[mt][nt][3]);
        }
    }
    for (int i = tid; i < 2304; i += 192) {
        int r = i / 48, c = (i % 48) * 4;
        float4 v = *(const float4*)(Cinv + r * 192 + c);
        uint32_t* p = &Fs[r * 196 + c];
        p[0] = cvt_tf32(v.x); p[1] = cvt_tf32(v.y);
        p[2] = cvt_tf32(v.z); p[3] = cvt_tf32(v.w);
    }
    __syncthreads();

    const int mt2 = w % 3, nh = w / 3;
    float a2[3][4];
    #pragma unroll
    for (int i = 0; i < 3; i++)
        #pragma unroll
        for (int d = 0; d < 4; d++) a2[i][d] = 0.f;

    #pragma unroll 8
    for (int kk = 0; kk < 192; kk += 8) {
        uint32_t af[4];
        const uint32_t* pa = &Fs[(mt2 * 16 + lr) * 196 + kk + lc];
        af[0] = pa[0]; af[1] = pa[1568]; af[2] = pa[4]; af[3] = pa[1572];
        #pragma unroll
        for (int nt = 0; nt < 3; nt++) {
            const uint32_t* pb = &Ts[(nh * 24 + nt * 8 + lr) * 196 + kk + lc];
            uint32_t bf[2] = { pb[0], pb[4] };
            mma_tf32(a2[nt], af, bf);
        }
    }
    // Y emitted as tf32 bits (gemmA consumes with ATF=true)
    uint32_t* Yn = Y + (size_t)n * 2304;
    #pragma unroll
    for (int nt = 0; nt < 3; nt++) {
        int r3 = mt2 * 16 + lr;
        int r2 = nh * 24 + nt * 8 + 2 * lc;
        Yn[r3 * 48 + r2]           = cvt_tf32(a2[nt][0]);
        Yn[r3 * 48 + r2 + 1]       = cvt_tf32(a2[nt][1]);
        Yn[(r3 + 8) * 48 + r2]     = cvt_tf32(a2[nt][2]);
        Yn[(r3 + 8) * 48 + r2 + 1] = cvt_tf32(a2[nt][3]);
    }
}

// ---------------------------------------------------------------------------
// Pipelined tf32 TC GEMM:  C[M,N] = A[M,K] @ B[N,K]^T
// ATF: A is pre-converted tf32 bits (no cvt in the inner loop).
// MINB: min blocks/SM passed to __launch_bounds__ (reg-cap control).
// Issue-before-wait double buffering.
// ---------------------------------------------------------------------------
template <int BM, int BN, int BK, int MW, int NW, bool ATF, int MINB>
__global__ void __launch_bounds__(256, MINB) k_gemm_tc_p(
    const void* __restrict__ Av, const uint32_t* __restrict__ B,
    float* __restrict__ C, int M, int N, int K)
{
    constexpr int WM = BM / MW, WN = BN / NW;
    constexpr int MT = WM / 16, NT = WN / 8;
    constexpr int LDSS = BK + 4;
    extern __shared__ uint32_t smg[];
    uint32_t* As = smg;                      // 2 x BM x LDSS (fp32 or tf32 bits)
    uint32_t* Bs = smg + 2 * BM * LDSS;      // 2 x BN x LDSS

    const float* A = (const float*)Av;       // 4-byte elements either way

    const int tid  = threadIdx.x;
    const int lane = tid & 31, warp = tid >> 5;
    const int wm = (warp / NW) * WM;
    const int wn = (warp % NW) * WN;
    const int m0 = blockIdx.y * BM;
    const int n0 = blockIdx.x * BN;
    const int lr = lane >> 2, lc = lane & 3;

    const uint32_t as_base = (uint32_t)__cvta_generic_to_shared(As);
    const uint32_t bs_base = (uint32_t)__cvta_generic_to_shared(Bs);

    auto load_stage = [&](int it, int buf) {
        const int k0 = it * BK;
        #pragma unroll
        for (int i = tid; i < BM * BK / 4; i += 256) {
            int r = i / (BK / 4), s = (i % (BK / 4)) * 4;
            cp_async16(as_base + (buf * BM * LDSS + r * LDSS + s) * 4,
                       A + (size_t)(m0 + r) * K + k0 + s);
        }
        #pragma unroll
        for (int i = tid; i < BN * BK / 4; i += 256) {
            int r = i / (BK / 4), s = (i % (BK / 4)) * 4;
            cp_async16(bs_base + (buf * BN * LDSS + r * LDSS + s) * 4,
                       B + (size_t)(n0 + r) * K + k0 + s);
        }
        asm volatile("cp.async.commit_group;");
    };

    float acc[MT][NT][4];
    #pragma unroll
    for (int i = 0; i < MT; i++)
        #pragma unroll
        for (int j = 0; j < NT; j++)
            #pragma unroll
            for (int d = 0; d < 4; d++) acc[i][j][d] = 0.f;

    load_stage(0, 0);
    const int iters = K / BK;

    for (int it = 0; it < iters; it++) {
        if (it + 1 < iters) {
            load_stage(it + 1, (it + 1) & 1);
            asm volatile("cp.async.wait_group 1;" ::: "memory");
        } else {
            asm volatile("cp.async.wait_group 0;" ::: "memory");
        }
        __syncthreads();
        const uint32_t* Ab = As + (it & 1) * BM * LDSS;
        const uint32_t* Bb = Bs + (it & 1) * BN * LDSS;

        #pragma unroll
        for (int kk = 0; kk < BK; kk += 8) {
            uint32_t af[MT][4], bf[NT][2];
            #pragma unroll
            for (int mt = 0; mt < MT; mt++) {
                const uint32_t* pa = Ab + (wm + mt * 16 + lr) * LDSS + kk + lc;
                if (ATF) {
                    af[mt][0] = pa[0];
                    af[mt][1] = pa[8 * LDSS];
                    af[mt][2] = pa[4];
                    af[mt][3] = pa[8 * LDSS + 4];
                } else {
                    af[mt][0] = cvt_tf32(__uint_as_float(pa[0]));
                    af[mt][1] = cvt_tf32(__uint_as_float(pa[8 * LDSS]));
                    af[mt][2] = cvt_tf32(__uint_as_float(pa[4]));
                    af[mt][3] = cvt_tf32(__uint_as_float(pa[8 * LDSS + 4]));
                }
            }
            #pragma unroll
            for (int nt = 0; nt < NT; nt++) {
                const uint32_t* pb = Bb + (wn + nt * 8 + lr) * LDSS + kk + lc;
                bf[nt][0] = pb[0];
                bf[nt][1] = pb[4];
            }
            #pragma unroll
            for (int mt = 0; mt < MT; mt++)
                #pragma unroll
                for (int nt = 0; nt < NT; nt++)
                    mma_tf32(acc[mt][nt], af[mt], bf[nt]);
        }
        __syncthreads();
    }

    #pragma unroll
    for (int mt = 0; mt < MT; mt++) {
        int r0 = m0 + wm + mt * 16 + lr;
        #pragma unroll
        for (int nt = 0; nt < NT; nt++) {
            int c0 = n0 + wn + nt * 8 + 2 * lc;
            *(float2*)(C + (size_t)r0 * N + c0)       = make_float2(acc[mt][nt][0], acc[mt][nt][1]);
            *(float2*)(C + (size_t)(r0 + 8) * N + c0) = make_float2(acc[mt][nt][2], acc[mt][nt][3]);
        }
    }
}

#define GEMMA_SMEM ((2*64*68 + 2*32*68) * 4)
#define GEMMS_SMEM ((2*128*36 + 2*128*36) * 4)

// ---------------------------------------------------------------------------
// Row softmax for A (2048 x 256): warp-per-row, shfl-only; output tf32 bits.
// ---------------------------------------------------------------------------
__global__ void __launch_bounds__(256) k_softmaxA(
    const float* __restrict__ A, uint32_t* __restrict__ out)
{
    const int w = threadIdx.x >> 5, lane = threadIdx.x & 31;
    const int n = blockIdx.x * 8 + w;
    const float4* a4 = (const float4*)(A + (size_t)n * 256);
    float4 v0 = a4[lane];
    float4 v1 = a4[lane + 32];

    float m = fmaxf(fmaxf(fmaxf(v0.x, v0.y), fmaxf(v0.z, v0.w)),
                    fmaxf(fmaxf(v1.x, v1.y), fmaxf(v1.z, v1.w)));
    #pragma unroll
    for (int o = 16; o > 0; o >>= 1) m = fmaxf(m, __shfl_xor_sync(0xffffffffu, m, o));

    float e0 = __expf(v0.x - m), e1 = __expf(v0.y - m);
    float e2 = __expf(v0.z - m), e3 = __expf(v0.w - m);
    float e4 = __expf(v1.x - m), e5 = __expf(v1.y - m);
    float e6 = __expf(v1.z - m), e7 = __expf(v1.w - m);
    float s = ((e0 + e1) + (e2 + e3)) + ((e4 + e5) + (e6 + e7));
    #pragma unroll
    for (int o = 16; o > 0; o >>= 1) s += __shfl_xor_sync(0xffffffffu, s, o);
    float inv = 1.f / s;

    uint4* o4 = (uint4*)(out + (size_t)n * 256);
    o4[lane]      = make_uint4(cvt_tf32(e0 * inv), cvt_tf32(e1 * inv),
                               cvt_tf32(e2 * inv), cvt_tf32(e3 * inv));
    o4[lane + 32] = make_uint4(cvt_tf32(e4 * inv), cvt_tf32(e5 * inv),
                               cvt_tf32(e6 * inv), cvt_tf32(e7 * inv));
}

// ---------------------------------------------------------------------------
// Fused decode: one CTA per sample n, 192 threads = 6 warps, 3 CTAs/SM.
// (R10-measured: stride-48 XOR swizzle, St/Bsm aliased, register-lean stage2.)
// ---------------------------------------------------------------------------
#define DEC_SMEM_U32 (192*48 + 192*48)
__global__ void __launch_bounds__(192, 3) k_dec(
    const float* __restrict__ S, const uint32_t* __restrict__ smB,
    const uint32_t* __restrict__ smC, float* __restrict__ out)
{
    extern __shared__ uint32_t smd[];
    uint32_t* Cs = smd;              // smC [k][r3] swizzled; then Ua [k][r2]
    uint32_t* R2 = smd + 192 * 48;   // St (48x48) then Bsm (192x48), swizzled

    const int n = blockIdx.x, tid = threadIdx.x;
    const int w = tid >> 5, lane = tid & 31;
    const int lr = lane >> 2, lc = lane & 3;
    const int sw = (lr & 6) << 1;

    for (int i = tid; i < 2304; i += 192) {
        int r = i / 12, c = (i % 12) * 4;
        uint4 v = *(const uint4*)(smC + r * 48 + c);
        uint32_t* p = &Cs[r * 48 + (c ^ ((r & 6) << 1))];
        p[0] = v.x; p[1] = v.y; p[2] = v.z; p[3] = v.w;
    }
    const float* Sn = S + (size_t)n * 2304;
    for (int i = tid; i < 576; i += 192) {
        int r3 = i / 12, r2 = (i % 12) * 4;
        float4 v = *(const float4*)(Sn + r3 * 48 + r2);
        R2[(r2 + 0) * 48 + (r3 ^ (((r2 + 0) & 6) << 1))] = cvt_tf32(v.x);
        R2[(r2 + 1) * 48 + (r3 ^ (((r2 + 1) & 6) << 1))] = cvt_tf32(v.y);
        R2[(r2 + 2) * 48 + (r3 ^ (((r2 + 2) & 6) << 1))] = cvt_tf32(v.z);
        R2[(r2 + 3) * 48 + (r3 ^ (((r2 + 3) & 6) << 1))] = cvt_tf32(v.w);
    }
    __syncthreads();

    float a1[2][6][4];
    #pragma unroll
    for (int i = 0; i < 2; i++)
        #pragma unroll
        for (int j = 0; j < 6; j++)
            #pragma unroll
            for (int d = 0; d < 4; d++) a1[i][j][d] = 0.f;

    #pragma unroll
    for (int kk = 0; kk < 48; kk += 8) {
        const int c0 = (kk ^ sw) + lc;
        const int c1 = ((kk + 4) ^ sw) + lc;
        uint32_t af[2][4], bf[6][2];
        #pragma unroll
        for (int mt = 0; mt < 2; mt++) {
            const uint32_t* pa = &Cs[(w * 32 + mt * 16 + lr) * 48];
            af[mt][0] = pa[c0]; af[mt][1] = pa[384 + c0];
            af[mt][2] = pa[c1]; af[mt][3] = pa[384 + c1];
        }
        #pragma unroll
        for (int nt = 0; nt < 6; nt++) {
            const uint32_t* pb = &R2[(nt * 8 + lr) * 48];
            bf[nt][0] = pb[c0]; bf[nt][1] = pb[c1];
        }
        #pragma unroll
        for (int mt = 0; mt < 2; mt++)
            #pragma unroll
            for (int nt = 0; nt < 6; nt++)
                mma_tf32(a1[mt][nt], af[mt], bf[nt]);
    }
    __syncthreads();

    #pragma unroll
    for (int mt = 0; mt < 2; mt++) {
        int k0 = w * 32 + mt * 16 + lr;
        #pragma unroll
        for (int nt = 0; nt < 6; nt++) {
            int cc = ((nt * 8 + 2 * lc) ^ sw);
            Cs[k0 * 48 + cc]           = cvt_tf32(a1[mt][nt][0]);
            Cs[k0 * 48 + cc + 1]       = cvt_tf32(a1[mt][nt][1]);
            Cs[(k0 + 8) * 48 + cc]     = cvt_tf32(a1[mt][nt][2]);
            Cs[(k0 + 8) * 48 + cc + 1] = cvt_tf32(a1[mt][nt][3]);
        }
    }
    for (int i = tid; i < 2304; i += 192) {
        int r = i / 12, c = (i % 12) * 4;
        uint4 v = *(const uint4*)(smB + r * 48 + c);
        uint32_t* p = &R2[r * 48 + (c ^ ((r & 6) << 1))];
        p[0] = v.x; p[1] = v.y; p[2] = v.z; p[3] = v.w;
    }
    __syncthreads();

    float* on = out + (size_t)n * 36864;
    const int wm = (w % 3) * 64;
    const int nb = (w / 3) * 24;
    #pragma unroll 1
    for (int np = 0; np < 4; np++) {
        const int wn = nb + np * 48;
        #pragma unroll 1
        for (int mp = 0; mp < 2; mp++) {
            const int mbase = wm + mp * 32;
            float a2[2][3][4];
            #pragma unroll
            for (int i = 0; i < 2; i++)
                #pragma unroll
                for (int j = 0; j < 3; j++)
                    #pragma unroll
                    for (int d = 0; d < 4; d++) a2[i][j][d] = 0.f;

            #pragma unroll
            for (int kk = 0; kk < 48; kk += 8) {
                const int c0 = (kk ^ sw) + lc;
                const int c1 = ((kk + 4) ^ sw) + lc;
                uint32_t af[2][4], bf[3][2];
                #pragma unroll
                for (int mt = 0; mt < 2; mt++) {
                    const uint32_t* pa = &Cs[(mbase + mt * 16 + lr) * 48];
                    af[mt][0] = pa[c0]; af[mt][1] = pa[384 + c0];
                    af[mt][2] = pa[c1]; af[mt][3] = pa[384 + c1];
                }
                #pragma unroll
                for (int nt = 0; nt < 3; nt++) {
                    const uint32_t* pb = &R2[(wn + nt * 8 + lr) * 48];
                    bf[nt][0] = pb[c0]; bf[nt][1] = pb[c1];
                }
                #pragma unroll
                for (int mt = 0; mt < 2; mt++)
                    #pragma unroll
                    for (int nt = 0; nt < 3; nt++)
                        mma_tf32(a2[mt][nt], af[mt], bf[nt]);
            }
            #pragma unroll
            for (int mt = 0; mt < 2; mt++) {
                int row = mbase + mt * 16 + lr;
                #pragma unroll
                for (int nt = 0; nt < 3; nt++) {
                    int col = wn + nt * 8 + 2 * lc;
                    *(float2*)(on + (size_t)row * 192 + col) =
                        make_float2(a2[mt][nt][0], a2[mt][nt][1]);
                    *(float2*)(on + (size_t)(row + 8) * 192 + col) =
                        make_float2(a2[mt][nt][2], a2[mt][nt][3]);
                }
            }
        }
    }
}

// ---------------------------------------------------------------------------
// Launch pipeline (default stream -> sequential; graph-capturable)
// ---------------------------------------------------------------------------
extern "C" void kernel_launch(void* const* d_in, const int* in_sizes, int n_in,
                              void* d_out, int out_size)
{
    const float* X     = (const float*)d_in[0];
    const float* B     = (const float*)d_in[1];
    const float* C     = (const float*)d_in[2];
    const float* G     = (const float*)d_in[3];
    const float* B_inv = (const float*)d_in[4];
    const float* C_inv = (const float*)d_in[5];
    const float* G_inv = (const float*)d_in[6];
    float* out = (float*)d_out;

    float *pBuf2, *pA;
    uint32_t *pSmA, *pSmBT, *pSmCT, *pGt, *pGrt;
    cudaGetSymbolAddress((void**)&pBuf2, g_buf2);
    cudaGetSymbolAddress((void**)&pA,    g_Amat);
    cudaGetSymbolAddress((void**)&pSmA,  g_smA);
    cudaGetSymbolAddress((void**)&pSmBT, g_smBT);
    cudaGetSymbolAddress((void**)&pSmCT, g_smCT);
    cudaGetSymbolAddress((void**)&pGt,   g_Gt);
    cudaGetSymbolAddress((void**)&pGrt,  g_Grt);

    cudaFuncSetAttribute(k_enc, cudaFuncAttributeMaxDynamicSharedMemorySize, ENC_SMEM_U32 * 4);
    cudaFuncSetAttribute(k_dec, cudaFuncAttributeMaxDynamicSharedMemorySize, DEC_SMEM_U32 * 4);
    cudaFuncSetAttribute((const void*)k_gemm_tc_p<64, 32, 64, 4, 2, true, 1>,
                         cudaFuncAttributeMaxDynamicSharedMemorySize, GEMMA_SMEM);
    cudaFuncSetAttribute((const void*)k_gemm_tc_p<128, 128, 32, 4, 2, true, 2>,
                         cudaFuncAttributeMaxDynamicSharedMemorySize, GEMMS_SMEM);

    // encode + prep in one launch; Y emitted as tf32 bits into g_buf2
    k_enc<<<PREP_BLOCKS + NSAMP, 192, ENC_SMEM_U32 * 4>>>(
        X, B_inv, C_inv, (uint32_t*)pBuf2, G_inv, G, B, C, pGt, pGrt, pSmBT, pSmCT);

    // A = Y(tf32) @ G_inv^T(tf32); softmax rows (output tf32 bits)
    k_gemm_tc_p<64, 32, 64, 4, 2, true, 1><<<dim3(8, 32), 256, GEMMA_SMEM>>>(
        pBuf2, pGt, pA, 2048, 256, 2304);
    k_softmaxA<<<256, 256>>>(pA, pSmA);

    // S = smA(tf32) @ relu(G)^T(tf32) -> fp32; 128x128 tile + 2 CTAs/SM (reg cap 128)
    k_gemm_tc_p<128, 128, 32, 4, 2, true, 2><<<dim3(18, 16), 256, GEMMS_SMEM>>>(
        pSmA, pGrt, pBuf2, 2048, 2304, 256);

    // decode: out[n] = (smC @ S[n]) @ smB^T
    k_dec<<<2048, 192, DEC_SMEM_U32 * 4>>>(pBuf2, pSmBT, pSmCT, out);
}

// round 16
// speedup vs baseline: 1.0492x; 1.0133x over previous
#include <cuda_runtime.h>
#include <cstdint>
#include <cstddef>

// Problem dims (fixed)
#define NSAMP 2048
#define JDIM  192
#define KDIM  192
#define R1D   256
#define R2D   48
#define R3D   48

#define PREP_BLOCKS 1154   // 576 Gt-transpose + 576 Grt-transpose + 2 softmax

// ---------------------------------------------------------------------------
// Scratch (__device__ globals; no allocation)
// ---------------------------------------------------------------------------
__device__ __align__(16) float    g_buf2[(size_t)NSAMP * R2D * R3D];    // Y(tf32 bits) then S(fp32)
__device__ __align__(16) float    g_Amat[(size_t)NSAMP * R1D];
__device__ __align__(16) uint32_t g_smA [(size_t)NSAMP * R1D];          // tf32 softmax(A)
__device__ __align__(16) uint32_t g_smBT [JDIM * R2D];     // tf32 softmax(B) (192x48)
__device__ __align__(16) uint32_t g_smCT [KDIM * R3D];     // tf32 softmax(C) (192x48)
__device__ __align__(16) uint32_t g_Gt   [R1D * 2304];     // tf32 G_inv^T (256x2304)
__device__ __align__(16) uint32_t g_Grt  [2304 * R1D];     // tf32 relu(G)^T (2304x256)

// ---------------------------------------------------------------------------
// tf32 helpers
// ---------------------------------------------------------------------------
__device__ __forceinline__ uint32_t cvt_tf32(float x) {
    uint32_t r;
    asm("cvt.rna.tf32.f32 %0, %1;" : "=r"(r) : "f"(x));
    return r;
}

__device__ __forceinline__ void mma_tf32(float* d, const uint32_t* a, const uint32_t* b) {
    asm volatile(
        "mma.sync.aligned.m16n8k8.row.col.f32.tf32.tf32.f32 "
        "{%0,%1,%2,%3},{%4,%5,%6,%7},{%8,%9},{%0,%1,%2,%3};"
        : "+f"(d[0]), "+f"(d[1]), "+f"(d[2]), "+f"(d[3])
        : "r"(a[0]), "r"(a[1]), "r"(a[2]), "r"(a[3]), "r"(b[0]), "r"(b[1]));
}

__device__ __forceinline__ void cp_async16(uint32_t smem_dst, const void* gsrc) {
    asm volatile("cp.async.cg.shared.global [%0], [%1], 16;" :: "r"(smem_dst), "l"(gsrc));
}

// ---------------------------------------------------------------------------
// Fused encode + prep: grid = PREP_BLOCKS + 2048, 192 threads, 3 CTAs/SM.
// stage1 uses warp-private X double buffers: zero block barriers in the
// 12-chunk main loop (per-thread cp.async wait + __syncwarp only).
// ---------------------------------------------------------------------------
#define ENC_SMEM_U32 (48*196 + 48*196)
__global__ void __launch_bounds__(192, 3) k_enc(
    const float* __restrict__ X, const float* __restrict__ Binv,
    const float* __restrict__ Cinv, uint32_t* __restrict__ Y,
    const float* __restrict__ Gi, const float* __restrict__ G,
    const float* __restrict__ Bm, const float* __restrict__ Cm,
    uint32_t* __restrict__ Gt, uint32_t* __restrict__ Grt,
    uint32_t* __restrict__ smBT, uint32_t* __restrict__ smCT)
{
    extern __shared__ uint32_t sme[];
    const int tid = threadIdx.x;

    // ---------------- prep branch ----------------
    if (blockIdx.x < PREP_BLOCKS) {
        int b = blockIdx.x;
        float* tile = (float*)sme;   // 32x33 floats
        if (b < 576) {
            int br = b >> 3, bc = b & 7;
            for (int i = tid; i < 1024; i += 192) {
                int r = i >> 5, c = i & 31;
                tile[r * 33 + c] = Gi[(size_t)(br * 32 + r) * 256 + bc * 32 + c];
            }
            __syncthreads();
            for (int i = tid; i < 1024; i += 192) {
                int r = i >> 5, c = i & 31;
                Gt[(size_t)(bc * 32 + r) * 2304 + br * 32 + c] = cvt_tf32(tile[c * 33 + r]);
            }
        } else if (b < 1152) {
            int b2 = b - 576;
            int br = b2 & 7, bc = b2 >> 3;
            for (int i = tid; i < 1024; i += 192) {
                int r = i >> 5, c = i & 31;
                tile[r * 33 + c] = G[(size_t)(br * 32 + r) * 2304 + bc * 32 + c];
            }
            __syncthreads();
            for (int i = tid; i < 1024; i += 192) {
                int r = i >> 5, c = i & 31;
                Grt[(size_t)(bc * 32 + r) * 256 + br * 32 + c] =
                    cvt_tf32(fmaxf(tile[c * 33 + r], 0.f));
            }
        } else {
            const float* in = (b == 1152) ? Bm : Cm;
            uint32_t* outp = (b == 1152) ? smBT : smCT;
            const float* p = in + tid * 48;
            float m = -1e30f;
            #pragma unroll
            for (int j = 0; j < 48; j++) m = fmaxf(m, p[j]);
            float s = 0.f;
            #pragma unroll
            for (int j = 0; j < 48; j++) s += __expf(p[j] - m);
            float inv = 1.f / s;
            #pragma unroll
            for (int j = 0; j < 48; j++)
                outp[tid * 48 + j] = cvt_tf32(__expf(p[j] - m) * inv);
        }
        return;
    }

    // ---------------- encode branch ----------------
    uint32_t* Fs = sme;                     // 48*196 tf32: Binv, later Cinv
    float*    Xf = (float*)(sme + 48*196);  // 6 warps x 2 bufs x 32 rows x 20
    uint32_t* Ts = sme + 48*196;            // later: T^T 48x196 tf32

    const int n = blockIdx.x - PREP_BLOCKS;
    const int w = tid >> 5, lane = tid & 31;
    const int lr = lane >> 2, lc = lane & 3;

    for (int i = tid; i < 2304; i += 192) {
        int r = i / 48, c = (i % 48) * 4;
        float4 v = *(const float4*)(Binv + r * 192 + c);
        uint32_t* p = &Fs[r * 196 + c];
        p[0] = cvt_tf32(v.x); p[1] = cvt_tf32(v.y);
        p[2] = cvt_tf32(v.z); p[3] = cvt_tf32(v.w);
    }
    __syncthreads();   // Fs visible before any warp's MMAs

    const uint32_t xs_base = (uint32_t)__cvta_generic_to_shared(Xf);
    const float* Xn = X + (size_t)n * 36864;
    const float* Xw = Xn + (size_t)(w * 32) * 192;   // this warp's 32 rows
    const uint32_t wbase = xs_base + (uint32_t)(w * 1280) * 4;

    // warp-private chunk loader: 32 rows x 16 cols (4 x 16B per lane)
    auto load_chunk = [&](int ck, int buf) {
        const float* src = Xw + ck * 16;
        const uint32_t dst = wbase + (uint32_t)(buf * 640) * 4;
        #pragma unroll
        for (int q = 0; q < 4; q++) {
            int i = lane + 32 * q;
            int row = i >> 2, seg = i & 3;
            cp_async16(dst + (row * 20 + seg * 4) * 4,
                       src + row * 192 + seg * 4);
        }
        asm volatile("cp.async.commit_group;");
    };

    load_chunk(0, 0);

    float acc[2][6][4];
    #pragma unroll
    for (int i = 0; i < 2; i++)
        #pragma unroll
        for (int j = 0; j < 6; j++)
            #pragma unroll
            for (int d = 0; d < 4; d++) acc[i][j][d] = 0.f;

    // warp-independent pipeline: no block barriers
    for (int ck = 0; ck < 12; ck++) {
        if (ck < 11) {
            load_chunk(ck + 1, (ck + 1) & 1);
            asm volatile("cp.async.wait_group 1;" ::: "memory");
        } else {
            asm volatile("cp.async.wait_group 0;" ::: "memory");
        }
        __syncwarp();
        const float* Xb = Xf + w * 1280 + (ck & 1) * 640;

        #pragma unroll
        for (int kk = 0; kk < 16; kk += 8) {
            uint32_t af[2][4], bf[6][2];
            #pragma unroll
            for (int mt = 0; mt < 2; mt++) {
                const float* pa = Xb + (mt * 16 + lr) * 20 + kk + lc;
                af[mt][0] = cvt_tf32(pa[0]);
                af[mt][1] = cvt_tf32(pa[160]);   // +8 rows
                af[mt][2] = cvt_tf32(pa[4]);
                af[mt][3] = cvt_tf32(pa[164]);
            }
            #pragma unroll
            for (int nt = 0; nt < 6; nt++) {
                const uint32_t* pb = &Fs[(nt * 8 + lr) * 196 + ck * 16 + kk + lc];
                bf[nt][0] = pb[0]; bf[nt][1] = pb[4];
            }
            #pragma unroll
            for (int mt = 0; mt < 2; mt++)
                #pragma unroll
                for (int nt = 0; nt < 6; nt++)
                    mma_tf32(acc[mt][nt], af[mt], bf[nt]);
        }
        __syncwarp();   // all lanes done reading buffer ck&1 before next overwrite
    }
    __syncthreads();   // stage1 done everywhere: Xf + Fs free for reuse

    // Store T transposed -> Ts[r2][k] (tf32, stride 196); overwrites X buffers
    #pragma unroll
    for (int mt = 0; mt < 2; mt++) {
        int k0 = w * 32 + mt * 16 + lr;
        #pragma unroll
        for (int nt = 0; nt < 6; nt++) {
            int r2 = nt * 8 + 2 * lc;
            Ts[r2 * 196 + k0]           = cvt_tf32(acc[mt][nt][0]);
            Ts[(r2 + 1) * 196 + k0]     = cvt_tf32(acc[mt][nt][1]);
            Ts[r2 * 196 + k0 + 8]       = cvt_tf32(acc[mt][nt][2]);
            Ts[(r2 + 1) * 196 + k0 + 8] = cvt_tf32(acc[mt][nt][3]);
        }
    }
    for (int i = tid; i < 2304; i += 192) {
        int r = i / 48, c = (i % 48) * 4;
        float4 v = *(const float4*)(Cinv + r * 192 + c);
        uint32_t* p = &Fs[r * 196 + c];
        p[0] = cvt_tf32(v.x); p[1] = cvt_tf32(v.y);
        p[2] = cvt_tf32(v.z); p[3] = cvt_tf32(v.w);
    }
    __syncthreads();

    const int mt2 = w % 3, nh = w / 3;
    float a2[3][4];
    #pragma unroll
    for (int i = 0; i < 3; i++)
        #pragma unroll
        for (int d = 0; d < 4; d++) a2[i][d] = 0.f;

    #pragma unroll 8
    for (int kk = 0; kk < 192; kk += 8) {
        uint32_t af[4];
        const uint32_t* pa = &Fs[(mt2 * 16 + lr) * 196 + kk + lc];
        af[0] = pa[0]; af[1] = pa[1568]; af[2] = pa[4]; af[3] = pa[1572];
        #pragma unroll
        for (int nt = 0; nt < 3; nt++) {
            const uint32_t* pb = &Ts[(nh * 24 + nt * 8 + lr) * 196 + kk + lc];
            uint32_t bf[2] = { pb[0], pb[4] };
            mma_tf32(a2[nt], af, bf);
        }
    }
    // Y emitted as tf32 bits (gemmA consumes with ATF=true)
    uint32_t* Yn = Y + (size_t)n * 2304;
    #pragma unroll
    for (int nt = 0; nt < 3; nt++) {
        int r3 = mt2 * 16 + lr;
        int r2 = nh * 24 + nt * 8 + 2 * lc;
        Yn[r3 * 48 + r2]           = cvt_tf32(a2[nt][0]);
        Yn[r3 * 48 + r2 + 1]       = cvt_tf32(a2[nt][1]);
        Yn[(r3 + 8) * 48 + r2]     = cvt_tf32(a2[nt][2]);
        Yn[(r3 + 8) * 48 + r2 + 1] = cvt_tf32(a2[nt][3]);
    }
}

// ---------------------------------------------------------------------------
// Pipelined tf32 TC GEMM:  C[M,N] = A[M,K] @ B[N,K]^T
// ATF: A is pre-converted tf32 bits.  MINB: __launch_bounds__ min blocks/SM.
// Issue-before-wait double buffering.
// ---------------------------------------------------------------------------
template <int BM, int BN, int BK, int MW, int NW, bool ATF, int MINB>
__global__ void __launch_bounds__(256, MINB) k_gemm_tc_p(
    const void* __restrict__ Av, const uint32_t* __restrict__ B,
    float* __restrict__ C, int M, int N, int K)
{
    constexpr int WM = BM / MW, WN = BN / NW;
    constexpr int MT = WM / 16, NT = WN / 8;
    constexpr int LDSS = BK + 4;
    extern __shared__ uint32_t smg[];
    uint32_t* As = smg;                      // 2 x BM x LDSS
    uint32_t* Bs = smg + 2 * BM * LDSS;      // 2 x BN x LDSS

    const float* A = (const float*)Av;

    const int tid  = threadIdx.x;
    const int lane = tid & 31, warp = tid >> 5;
    const int wm = (warp / NW) * WM;
    const int wn = (warp % NW) * WN;
    const int m0 = blockIdx.y * BM;
    const int n0 = blockIdx.x * BN;
    const int lr = lane >> 2, lc = lane & 3;

    const uint32_t as_base = (uint32_t)__cvta_generic_to_shared(As);
    const uint32_t bs_base = (uint32_t)__cvta_generic_to_shared(Bs);

    auto load_stage = [&](int it, int buf) {
        const int k0 = it * BK;
        #pragma unroll
        for (int i = tid; i < BM * BK / 4; i += 256) {
            int r = i / (BK / 4), s = (i % (BK / 4)) * 4;
            cp_async16(as_base + (buf * BM * LDSS + r * LDSS + s) * 4,
                       A + (size_t)(m0 + r) * K + k0 + s);
        }
        #pragma unroll
        for (int i = tid; i < BN * BK / 4; i += 256) {
            int r = i / (BK / 4), s = (i % (BK / 4)) * 4;
            cp_async16(bs_base + (buf * BN * LDSS + r * LDSS + s) * 4,
                       B + (size_t)(n0 + r) * K + k0 + s);
        }
        asm volatile("cp.async.commit_group;");
    };

    float acc[MT][NT][4];
    #pragma unroll
    for (int i = 0; i < MT; i++)
        #pragma unroll
        for (int j = 0; j < NT; j++)
            #pragma unroll
            for (int d = 0; d < 4; d++) acc[i][j][d] = 0.f;

    load_stage(0, 0);
    const int iters = K / BK;

    for (int it = 0; it < iters; it++) {
        if (it + 1 < iters) {
            load_stage(it + 1, (it + 1) & 1);
            asm volatile("cp.async.wait_group 1;" ::: "memory");
        } else {
            asm volatile("cp.async.wait_group 0;" ::: "memory");
        }
        __syncthreads();
        const uint32_t* Ab = As + (it & 1) * BM * LDSS;
        const uint32_t* Bb = Bs + (it & 1) * BN * LDSS;

        #pragma unroll
        for (int kk = 0; kk < BK; kk += 8) {
            uint32_t af[MT][4], bf[NT][2];
            #pragma unroll
            for (int mt = 0; mt < MT; mt++) {
                const uint32_t* pa = Ab + (wm + mt * 16 + lr) * LDSS + kk + lc;
                if (ATF) {
                    af[mt][0] = pa[0];
                    af[mt][1] = pa[8 * LDSS];
                    af[mt][2] = pa[4];
                    af[mt][3] = pa[8 * LDSS + 4];
                } else {
                    af[mt][0] = cvt_tf32(__uint_as_float(pa[0]));
                    af[mt][1] = cvt_tf32(__uint_as_float(pa[8 * LDSS]));
                    af[mt][2] = cvt_tf32(__uint_as_float(pa[4]));
                    af[mt][3] = cvt_tf32(__uint_as_float(pa[8 * LDSS + 4]));
                }
            }
            #pragma unroll
            for (int nt = 0; nt < NT; nt++) {
                const uint32_t* pb = Bb + (wn + nt * 8 + lr) * LDSS + kk + lc;
                bf[nt][0] = pb[0];
                bf[nt][1] = pb[4];
            }
            #pragma unroll
            for (int mt = 0; mt < MT; mt++)
                #pragma unroll
                for (int nt = 0; nt < NT; nt++)
                    mma_tf32(acc[mt][nt], af[mt], bf[nt]);
        }
        __syncthreads();
    }

    #pragma unroll
    for (int mt = 0; mt < MT; mt++) {
        int r0 = m0 + wm + mt * 16 + lr;
        #pragma unroll
        for (int nt = 0; nt < NT; nt++) {
            int c0 = n0 + wn + nt * 8 + 2 * lc;
            *(float2*)(C + (size_t)r0 * N + c0)       = make_float2(acc[mt][nt][0], acc[mt][nt][1]);
            *(float2*)(C + (size_t)(r0 + 8) * N + c0) = make_float2(acc[mt][nt][2], acc[mt][nt][3]);
        }
    }
}

#define GEMMA_SMEM ((2*64*68 + 2*32*68) * 4)
#define GEMMS_SMEM ((2*128*36 + 2*128*36) * 4)

// ---------------------------------------------------------------------------
// Row softmax for A (2048 x 256): warp-per-row, shfl-only; output tf32 bits.
// ---------------------------------------------------------------------------
__global__ void __launch_bounds__(256) k_softmaxA(
    const float* __restrict__ A, uint32_t* __restrict__ out)
{
    const int w = threadIdx.x >> 5, lane = threadIdx.x & 31;
    const int n = blockIdx.x * 8 + w;
    const float4* a4 = (const float4*)(A + (size_t)n * 256);
    float4 v0 = a4[lane];
    float4 v1 = a4[lane + 32];

    float m = fmaxf(fmaxf(fmaxf(v0.x, v0.y), fmaxf(v0.z, v0.w)),
                    fmaxf(fmaxf(v1.x, v1.y), fmaxf(v1.z, v1.w)));
    #pragma unroll
    for (int o = 16; o > 0; o >>= 1) m = fmaxf(m, __shfl_xor_sync(0xffffffffu, m, o));

    float e0 = __expf(v0.x - m), e1 = __expf(v0.y - m);
    float e2 = __expf(v0.z - m), e3 = __expf(v0.w - m);
    float e4 = __expf(v1.x - m), e5 = __expf(v1.y - m);
    float e6 = __expf(v1.z - m), e7 = __expf(v1.w - m);
    float s = ((e0 + e1) + (e2 + e3)) + ((e4 + e5) + (e6 + e7));
    #pragma unroll
    for (int o = 16; o > 0; o >>= 1) s += __shfl_xor_sync(0xffffffffu, s, o);
    float inv = 1.f / s;

    uint4* o4 = (uint4*)(out + (size_t)n * 256);
    o4[lane]      = make_uint4(cvt_tf32(e0 * inv), cvt_tf32(e1 * inv),
                               cvt_tf32(e2 * inv), cvt_tf32(e3 * inv));
    o4[lane + 32] = make_uint4(cvt_tf32(e4 * inv), cvt_tf32(e5 * inv),
                               cvt_tf32(e6 * inv), cvt_tf32(e7 * inv));
}

// ---------------------------------------------------------------------------
// Fused decode: one CTA per sample n, 192 threads = 6 warps, 3 CTAs/SM.
// (R10-measured: stride-48 XOR swizzle, St/Bsm aliased, register-lean stage2.)
// ---------------------------------------------------------------------------
#define DEC_SMEM_U32 (192*48 + 192*48)
__global__ void __launch_bounds__(192, 3) k_dec(
    const float* __restrict__ S, const uint32_t* __restrict__ smB,
    const uint32_t* __restrict__ smC, float* __restrict__ out)
{
    extern __shared__ uint32_t smd[];
    uint32_t* Cs = smd;              // smC [k][r3] swizzled; then Ua [k][r2]
    uint32_t* R2 = smd + 192 * 48;   // St (48x48) then Bsm (192x48), swizzled

    const int n = blockIdx.x, tid = threadIdx.x;
    const int w = tid >> 5, lane = tid & 31;
    const int lr = lane >> 2, lc = lane & 3;
    const int sw = (lr & 6) << 1;

    for (int i = tid; i < 2304; i += 192) {
        int r = i / 12, c = (i % 12) * 4;
        uint4 v = *(const uint4*)(smC + r * 48 + c);
        uint32_t* p = &Cs[r * 48 + (c ^ ((r & 6) << 1))];
        p[0] = v.x; p[1] = v.y; p[2] = v.z; p[3] = v.w;
    }
    const float* Sn = S + (size_t)n * 2304;
    for (int i = tid; i < 576; i += 192) {
        int r3 = i / 12, r2 = (i % 12) * 4;
        float4 v = *(const float4*)(Sn + r3 * 48 + r2);
        R2[(r2 + 0) * 48 + (r3 ^ (((r2 + 0) & 6) << 1))] = cvt_tf32(v.x);
        R2[(r2 + 1) * 48 + (r3 ^ (((r2 + 1) & 6) << 1))] = cvt_tf32(v.y);
        R2[(r2 + 2) * 48 + (r3 ^ (((r2 + 2) & 6) << 1))] = cvt_tf32(v.z);
        R2[(r2 + 3) * 48 + (r3 ^ (((r2 + 3) & 6) << 1))] = cvt_tf32(v.w);
    }
    __syncthreads();

    float a1[2][6][4];
    #pragma unroll
    for (int i = 0; i < 2; i++)
        #pragma unroll
        for (int j = 0; j < 6; j++)
            #pragma unroll
            for (int d = 0; d < 4; d++) a1[i][j][d] = 0.f;

    #pragma unroll
    for (int kk = 0; kk < 48; kk += 8) {
        const int c0 = (kk ^ sw) + lc;
        const int c1 = ((kk + 4) ^ sw) + lc;
        uint32_t af[2][4], bf[6][2];
        #pragma unroll
        for (int mt = 0; mt < 2; mt++) {
            const uint32_t* pa = &Cs[(w * 32 + mt * 16 + lr) * 48];
            af[mt][0] = pa[c0]; af[mt][1] = pa[384 + c0];
            af[mt][2] = pa[c1]; af[mt][3] = pa[384 + c1];
        }
        #pragma unroll
        for (int nt = 0; nt < 6; nt++) {
            const uint32_t* pb = &R2[(nt * 8 + lr) * 48];
            bf[nt][0] = pb[c0]; bf[nt][1] = pb[c1];
        }
        #pragma unroll
        for (int mt = 0; mt < 2; mt++)
            #pragma unroll
            for (int nt = 0; nt < 6; nt++)
                mma_tf32(a1[mt][nt], af[mt], bf[nt]);
    }
    __syncthreads();

    #pragma unroll
    for (int mt = 0; mt < 2; mt++) {
        int k0 = w * 32 + mt * 16 + lr;
        #pragma unroll
        for (int nt = 0; nt < 6; nt++) {
            int cc = ((nt * 8 + 2 * lc) ^ sw);
            Cs[k0 * 48 + cc]           = cvt_tf32(a1[mt][nt][0]);
            Cs[k0 * 48 + cc + 1]       = cvt_tf32(a1[mt][nt][1]);
            Cs[(k0 + 8) * 48 + cc]     = cvt_tf32(a1[mt][nt][2]);
            Cs[(k0 + 8) * 48 + cc + 1] = cvt_tf32(a1[mt][nt][3]);
        }
    }
    for (int i = tid; i < 2304; i += 192) {
        int r = i / 12, c = (i % 12) * 4;
        uint4 v = *(const uint4*)(smB + r * 48 + c);
        uint32_t* p = &R2[r * 48 + (c ^ ((r & 6) << 1))];
        p[0] = v.x; p[1] = v.y; p[2] = v.z; p[3] = v.w;
    }
    __syncthreads();

    float* on = out + (size_t)n * 36864;
    const int wm = (w % 3) * 64;
    const int nb = (w / 3) * 24;
    #pragma unroll 1
    for (int np = 0; np < 4; np++) {
        const int wn = nb + np * 48;
        #pragma unroll 1
        for (int mp = 0; mp < 2; mp++) {
            const int mbase = wm + mp * 32;
            float a2[2][3][4];
            #pragma unroll
            for (int i = 0; i < 2; i++)
                #pragma unroll
                for (int j = 0; j < 3; j++)
                    #pragma unroll
                    for (int d = 0; d < 4; d++) a2[i][j][d] = 0.f;

            #pragma unroll
            for (int kk = 0; kk < 48; kk += 8) {
                const int c0 = (kk ^ sw) + lc;
                const int c1 = ((kk + 4) ^ sw) + lc;
                uint32_t af[2][4], bf[3][2];
                #pragma unroll
                for (int mt = 0; mt < 2; mt++) {
                    const uint32_t* pa = &Cs[(mbase + mt * 16 + lr) * 48];
                    af[mt][0] = pa[c0]; af[mt][1] = pa[384 + c0];
                    af[mt][2] = pa[c1]; af[mt][3] = pa[384 + c1];
                }
                #pragma unroll
                for (int nt = 0; nt < 3; nt++) {
                    const uint32_t* pb = &R2[(wn + nt * 8 + lr) * 48];
                    bf[nt][0] = pb[c0]; bf[nt][1] = pb[c1];
                }
                #pragma unroll
                for (int mt = 0; mt < 2; mt++)
                    #pragma unroll
                    for (int nt = 0; nt < 3; nt++)
                        mma_tf32(a2[mt][nt], af[mt], bf[nt]);
            }
            #pragma unroll
            for (int mt = 0; mt < 2; mt++) {
                int row = mbase + mt * 16 + lr;
                #pragma unroll
                for (int nt = 0; nt < 3; nt++) {
                    int col = wn + nt * 8 + 2 * lc;
                    *(float2*)(on + (size_t)row * 192 + col) =
                        make_float2(a2[mt][nt][0], a2[mt][nt][1]);
                    *(float2*)(on + (size_t)(row + 8) * 192 + col) =
                        make_float2(a2[mt][nt][2], a2[mt][nt][3]);
                }
            }
        }
    }
}

// ---------------------------------------------------------------------------
// Launch pipeline (default stream -> sequential; graph-capturable)
// ---------------------------------------------------------------------------
extern "C" void kernel_launch(void* const* d_in, const int* in_sizes, int n_in,
                              void* d_out, int out_size)
{
    const float* X     = (const float*)d_in[0];
    const float* B     = (const float*)d_in[1];
    const float* C     = (const float*)d_in[2];
    const float* G     = (const float*)d_in[3];
    const float* B_inv = (const float*)d_in[4];
    const float* C_inv = (const float*)d_in[5];
    const float* G_inv = (const float*)d_in[6];
    float* out = (float*)d_out;

    float *pBuf2, *pA;
    uint32_t *pSmA, *pSmBT, *pSmCT, *pGt, *pGrt;
    cudaGetSymbolAddress((void**)&pBuf2, g_buf2);
    cudaGetSymbolAddress((void**)&pA,    g_Amat);
    cudaGetSymbolAddress((void**)&pSmA,  g_smA);
    cudaGetSymbolAddress((void**)&pSmBT, g_smBT);
    cudaGetSymbolAddress((void**)&pSmCT, g_smCT);
    cudaGetSymbolAddress((void**)&pGt,   g_Gt);
    cudaGetSymbolAddress((void**)&pGrt,  g_Grt);

    cudaFuncSetAttribute(k_enc, cudaFuncAttributeMaxDynamicSharedMemorySize, ENC_SMEM_U32 * 4);
    cudaFuncSetAttribute(k_dec, cudaFuncAttributeMaxDynamicSharedMemorySize, DEC_SMEM_U32 * 4);
    cudaFuncSetAttribute((const void*)k_gemm_tc_p<64, 32, 64, 4, 2, true, 1>,
                         cudaFuncAttributeMaxDynamicSharedMemorySize, GEMMA_SMEM);
    cudaFuncSetAttribute((const void*)k_gemm_tc_p<128, 128, 32, 4, 2, true, 2>,
                         cudaFuncAttributeMaxDynamicSharedMemorySize, GEMMS_SMEM);

    // encode + prep in one launch; Y emitted as tf32 bits into g_buf2
    k_enc<<<PREP_BLOCKS + NSAMP, 192, ENC_SMEM_U32 * 4>>>(
        X, B_inv, C_inv, (uint32_t*)pBuf2, G_inv, G, B, C, pGt, pGrt, pSmBT, pSmCT);

    // A = Y(tf32) @ G_inv^T(tf32); softmax rows (output tf32 bits)
    k_gemm_tc_p<64, 32, 64, 4, 2, true, 1><<<dim3(8, 32), 256, GEMMA_SMEM>>>(
        pBuf2, pGt, pA, 2048, 256, 2304);
    k_softmaxA<<<256, 256>>>(pA, pSmA);

    // S = smA(tf32) @ relu(G)^T(tf32) -> fp32; 128x128 tile, 2 CTAs/SM
    k_gemm_tc_p<128, 128, 32, 4, 2, true, 2><<<dim3(18, 16), 256, GEMMS_SMEM>>>(
        pSmA, pGrt, pBuf2, 2048, 2304, 256);

    // decode: out[n] = (smC @ S[n]) @ smB^T
    k_dec<<<2048, 192, DEC_SMEM_U32 * 4>>>(pBuf2, pSmBT, pSmCT, out);
}

// round 17
// speedup vs baseline: 1.1182x; 1.0657x over previous
#include <cuda_runtime.h>
#include <cuda_fp16.h>
#include <cstdint>
#include <cstddef>

// Problem dims (fixed)
#define NSAMP 2048
#define JDIM  192
#define KDIM  192
#define R1D   256
#define R2D   48
#define R3D   48

#define PREP_BLOCKS 1154   // 576 Gt-transpose + 576 Grt-transpose + 2 softmax

// ---------------------------------------------------------------------------
// Scratch (__device__ globals; no allocation)
// ---------------------------------------------------------------------------
__device__ __align__(16) float    g_buf2[(size_t)NSAMP * R2D * R3D];    // Y(tf32 bits) then S(fp32)
__device__ __align__(16) float    g_Amat[(size_t)NSAMP * R1D];
__device__ __align__(16) uint32_t g_smA [(size_t)NSAMP * R1D];          // tf32 softmax(A)
__device__ __align__(16) uint32_t g_smBT [JDIM * R2D];     // tf32 softmax(B) (192x48)
__device__ __align__(16) uint32_t g_smCT [KDIM * R3D];     // tf32 softmax(C) (192x48)
__device__ __align__(16) uint32_t g_Gt   [R1D * 2304];     // tf32 G_inv^T (256x2304)
__device__ __align__(16) uint32_t g_Grt  [2304 * R1D];     // tf32 relu(G)^T (2304x256)

// ---------------------------------------------------------------------------
// helpers
// ---------------------------------------------------------------------------
__device__ __forceinline__ uint32_t cvt_tf32(float x) {
    uint32_t r;
    asm("cvt.rna.tf32.f32 %0, %1;" : "=r"(r) : "f"(x));
    return r;
}

__device__ __forceinline__ uint32_t packh2(float a, float b) {
    __half2 h = __floats2half2_rn(a, b);
    return *reinterpret_cast<uint32_t*>(&h);
}

__device__ __forceinline__ void mma_tf32(float* d, const uint32_t* a, const uint32_t* b) {
    asm volatile(
        "mma.sync.aligned.m16n8k8.row.col.f32.tf32.tf32.f32 "
        "{%0,%1,%2,%3},{%4,%5,%6,%7},{%8,%9},{%0,%1,%2,%3};"
        : "+f"(d[0]), "+f"(d[1]), "+f"(d[2]), "+f"(d[3])
        : "r"(a[0]), "r"(a[1]), "r"(a[2]), "r"(a[3]), "r"(b[0]), "r"(b[1]));
}

__device__ __forceinline__ void mma_f16(float* d, const uint32_t* a, const uint32_t* b) {
    asm volatile(
        "mma.sync.aligned.m16n8k16.row.col.f32.f16.f16.f32 "
        "{%0,%1,%2,%3},{%4,%5,%6,%7},{%8,%9},{%0,%1,%2,%3};"
        : "+f"(d[0]), "+f"(d[1]), "+f"(d[2]), "+f"(d[3])
        : "r"(a[0]), "r"(a[1]), "r"(a[2]), "r"(a[3]), "r"(b[0]), "r"(b[1]));
}

__device__ __forceinline__ void cp_async16(uint32_t smem_dst, const void* gsrc) {
    asm volatile("cp.async.cg.shared.global [%0], [%1], 16;" :: "r"(smem_dst), "l"(gsrc));
}

// ---------------------------------------------------------------------------
// Fused encode + prep: grid = PREP_BLOCKS + 2048, 192 threads, 3 CTAs/SM.
// stage1: fp16 m16n8k16 (X packed fp32->h2 at fragment load; Binv staged half).
// stage2: tf32 (unchanged). Warp-private X double buffers, no block barriers.
// ---------------------------------------------------------------------------
#define ENC_SMEM_U32 (48*196 + 48*196)
__global__ void __launch_bounds__(192, 3) k_enc(
    const float* __restrict__ X, const float* __restrict__ Binv,
    const float* __restrict__ Cinv, uint32_t* __restrict__ Y,
    const float* __restrict__ Gi, const float* __restrict__ G,
    const float* __restrict__ Bm, const float* __restrict__ Cm,
    uint32_t* __restrict__ Gt, uint32_t* __restrict__ Grt,
    uint32_t* __restrict__ smBT, uint32_t* __restrict__ smCT)
{
    extern __shared__ uint32_t sme[];
    const int tid = threadIdx.x;

    // ---------------- prep branch ----------------
    if (blockIdx.x < PREP_BLOCKS) {
        int b = blockIdx.x;
        float* tile = (float*)sme;   // 32x33 floats
        if (b < 576) {
            int br = b >> 3, bc = b & 7;
            for (int i = tid; i < 1024; i += 192) {
                int r = i >> 5, c = i & 31;
                tile[r * 33 + c] = Gi[(size_t)(br * 32 + r) * 256 + bc * 32 + c];
            }
            __syncthreads();
            for (int i = tid; i < 1024; i += 192) {
                int r = i >> 5, c = i & 31;
                Gt[(size_t)(bc * 32 + r) * 2304 + br * 32 + c] = cvt_tf32(tile[c * 33 + r]);
            }
        } else if (b < 1152) {
            int b2 = b - 576;
            int br = b2 & 7, bc = b2 >> 3;
            for (int i = tid; i < 1024; i += 192) {
                int r = i >> 5, c = i & 31;
                tile[r * 33 + c] = G[(size_t)(br * 32 + r) * 2304 + bc * 32 + c];
            }
            __syncthreads();
            for (int i = tid; i < 1024; i += 192) {
                int r = i >> 5, c = i & 31;
                Grt[(size_t)(bc * 32 + r) * 256 + br * 32 + c] =
                    cvt_tf32(fmaxf(tile[c * 33 + r], 0.f));
            }
        } else {
            const float* in = (b == 1152) ? Bm : Cm;
            uint32_t* outp = (b == 1152) ? smBT : smCT;
            const float* p = in + tid * 48;
            float m = -1e30f;
            #pragma unroll
            for (int j = 0; j < 48; j++) m = fmaxf(m, p[j]);
            float s = 0.f;
            #pragma unroll
            for (int j = 0; j < 48; j++) s += __expf(p[j] - m);
            float inv = 1.f / s;
            #pragma unroll
            for (int j = 0; j < 48; j++)
                outp[tid * 48 + j] = cvt_tf32(__expf(p[j] - m) * inv);
        }
        return;
    }

    // ---------------- encode branch ----------------
    uint32_t* Fs  = sme;                      // stage2: Cinv tf32 (48 x 196)
    uint32_t* FsH2 = sme;                     // stage1: Binv half, stride 200 halves (u32 view)
    float*    Xf  = (float*)(sme + 48*196);   // 6 warps x 2 bufs x 32 rows x 24 fp32
    uint32_t* Ts  = sme + 48*196;             // later: T^T 48x196 tf32

    const int n = blockIdx.x - PREP_BLOCKS;
    const int w = tid >> 5, lane = tid & 31;
    const int lr = lane >> 2, lc = lane & 3;

    // Binv (48x192 fp32) -> half, row stride 200 halves (=100 u32)
    for (int i = tid; i < 2304; i += 192) {
        int r = i / 48, c = (i % 48) * 4;
        float4 v = *(const float4*)(Binv + r * 192 + c);
        uint32_t* p = &FsH2[r * 100 + (c >> 1)];
        p[0] = packh2(v.x, v.y);
        p[1] = packh2(v.z, v.w);
    }
    __syncthreads();   // Fs visible before any warp's MMAs

    const uint32_t xs_base = (uint32_t)__cvta_generic_to_shared(Xf);
    const float* Xn = X + (size_t)n * 36864;
    const float* Xw = Xn + (size_t)(w * 32) * 192;   // this warp's 32 rows
    const uint32_t wbase = xs_base + (uint32_t)(w * 1536) * 4;

    // warp-private chunk loader: 32 rows x 16 cols, smem row stride 24 fp32
    auto load_chunk = [&](int ck, int buf) {
        const float* src = Xw + ck * 16;
        const uint32_t dst = wbase + (uint32_t)(buf * 768) * 4;
        #pragma unroll
        for (int q = 0; q < 4; q++) {
            int i = lane + 32 * q;
            int row = i >> 2, seg = i & 3;
            cp_async16(dst + (row * 24 + seg * 4) * 4,
                       src + row * 192 + seg * 4);
        }
        asm volatile("cp.async.commit_group;");
    };

    load_chunk(0, 0);

    float acc[2][6][4];
    #pragma unroll
    for (int i = 0; i < 2; i++)
        #pragma unroll
        for (int j = 0; j < 6; j++)
            #pragma unroll
            for (int d = 0; d < 4; d++) acc[i][j][d] = 0.f;

    // warp-independent fp16 pipeline: 1 m16n8k16 step per 16-col chunk
    for (int ck = 0; ck < 12; ck++) {
        if (ck < 11) {
            load_chunk(ck + 1, (ck + 1) & 1);
            asm volatile("cp.async.wait_group 1;" ::: "memory");
        } else {
            asm volatile("cp.async.wait_group 0;" ::: "memory");
        }
        __syncwarp();
        const float* Xb = Xf + w * 1536 + (ck & 1) * 768;

        uint32_t af[2][4], bf[6][2];
        #pragma unroll
        for (int mt = 0; mt < 2; mt++) {
            const float* pa = Xb + (mt * 16 + lr) * 24;
            float2 x0 = *(const float2*)(pa + 2 * lc);            // rows lr,   k 2lc..
            float2 x1 = *(const float2*)(pa + 192 + 2 * lc);      // rows lr+8 (8*24)
            float2 x2 = *(const float2*)(pa + 2 * lc + 8);        // k +8
            float2 x3 = *(const float2*)(pa + 192 + 2 * lc + 8);
            af[mt][0] = packh2(x0.x, x0.y);
            af[mt][1] = packh2(x1.x, x1.y);
            af[mt][2] = packh2(x2.x, x2.y);
            af[mt][3] = packh2(x3.x, x3.y);
        }
        #pragma unroll
        for (int nt = 0; nt < 6; nt++) {
            const uint32_t* pb = &FsH2[(nt * 8 + lr) * 100 + ck * 8 + lc];
            bf[nt][0] = pb[0];
            bf[nt][1] = pb[4];   // k +8 halves
        }
        #pragma unroll
        for (int mt = 0; mt < 2; mt++)
            #pragma unroll
            for (int nt = 0; nt < 6; nt++)
                mma_f16(acc[mt][nt], af[mt], bf[nt]);
        __syncwarp();   // all lanes done reading buffer ck&1 before overwrite
    }
    __syncthreads();   // stage1 done everywhere: Xf + Fs free for reuse

    // Store T transposed -> Ts[r2][k] (tf32, stride 196); overwrites X buffers
    #pragma unroll
    for (int mt = 0; mt < 2; mt++) {
        int k0 = w * 32 + mt * 16 + lr;
        #pragma unroll
        for (int nt = 0; nt < 6; nt++) {
            int r2 = nt * 8 + 2 * lc;
            Ts[r2 * 196 + k0]           = cvt_tf32(acc[mt][nt][0]);
            Ts[(r2 + 1) * 196 + k0]     = cvt_tf32(acc[mt][nt][1]);
            Ts[r2 * 196 + k0 + 8]       = cvt_tf32(acc[mt][nt][2]);
            Ts[(r2 + 1) * 196 + k0 + 8] = cvt_tf32(acc[mt][nt][3]);
        }
    }
    // Load C_inv (tf32) over the Binv region
    for (int i = tid; i < 2304; i += 192) {
        int r = i / 48, c = (i % 48) * 4;
        float4 v = *(const float4*)(Cinv + r * 192 + c);
        uint32_t* p = &Fs[r * 196 + c];
        p[0] = cvt_tf32(v.x); p[1] = cvt_tf32(v.y);
        p[2] = cvt_tf32(v.z); p[3] = cvt_tf32(v.w);
    }
    __syncthreads();

    // stage2: Y = Cinv(48x192) @ T(192x48), tf32 (unchanged)
    const int mt2 = w % 3, nh = w / 3;
    float a2[3][4];
    #pragma unroll
    for (int i = 0; i < 3; i++)
        #pragma unroll
        for (int d = 0; d < 4; d++) a2[i][d] = 0.f;

    #pragma unroll 8
    for (int kk = 0; kk < 192; kk += 8) {
        uint32_t af[4];
        const uint32_t* pa = &Fs[(mt2 * 16 + lr) * 196 + kk + lc];
        af[0] = pa[0]; af[1] = pa[1568]; af[2] = pa[4]; af[3] = pa[1572];
        #pragma unroll
        for (int nt = 0; nt < 3; nt++) {
            const uint32_t* pb = &Ts[(nh * 24 + nt * 8 + lr) * 196 + kk + lc];
            uint32_t bf[2] = { pb[0], pb[4] };
            mma_tf32(a2[nt], af, bf);
        }
    }
    uint32_t* Yn = Y + (size_t)n * 2304;
    #pragma unroll
    for (int nt = 0; nt < 3; nt++) {
        int r3 = mt2 * 16 + lr;
        int r2 = nh * 24 + nt * 8 + 2 * lc;
        Yn[r3 * 48 + r2]           = cvt_tf32(a2[nt][0]);
        Yn[r3 * 48 + r2 + 1]       = cvt_tf32(a2[nt][1]);
        Yn[(r3 + 8) * 48 + r2]     = cvt_tf32(a2[nt][2]);
        Yn[(r3 + 8) * 48 + r2 + 1] = cvt_tf32(a2[nt][3]);
    }
}

// ---------------------------------------------------------------------------
// Pipelined tf32 TC GEMM (R16-measured).
// ---------------------------------------------------------------------------
template <int BM, int BN, int BK, int MW, int NW, bool ATF, int MINB>
__global__ void __launch_bounds__(256, MINB) k_gemm_tc_p(
    const void* __restrict__ Av, const uint32_t* __restrict__ B,
    float* __restrict__ C, int M, int N, int K)
{
    constexpr int WM = BM / MW, WN = BN / NW;
    constexpr int MT = WM / 16, NT = WN / 8;
    constexpr int LDSS = BK + 4;
    extern __shared__ uint32_t smg[];
    uint32_t* As = smg;
    uint32_t* Bs = smg + 2 * BM * LDSS;

    const float* A = (const float*)Av;

    const int tid  = threadIdx.x;
    const int lane = tid & 31, warp = tid >> 5;
    const int wm = (warp / NW) * WM;
    const int wn = (warp % NW) * WN;
    const int m0 = blockIdx.y * BM;
    const int n0 = blockIdx.x * BN;
    const int lr = lane >> 2, lc = lane & 3;

    const uint32_t as_base = (uint32_t)__cvta_generic_to_shared(As);
    const uint32_t bs_base = (uint32_t)__cvta_generic_to_shared(Bs);

    auto load_stage = [&](int it, int buf) {
        const int k0 = it * BK;
        #pragma unroll
        for (int i = tid; i < BM * BK / 4; i += 256) {
            int r = i / (BK / 4), s = (i % (BK / 4)) * 4;
            cp_async16(as_base + (buf * BM * LDSS + r * LDSS + s) * 4,
                       A + (size_t)(m0 + r) * K + k0 + s);
        }
        #pragma unroll
        for (int i = tid; i < BN * BK / 4; i += 256) {
            int r = i / (BK / 4), s = (i % (BK / 4)) * 4;
            cp_async16(bs_base + (buf * BN * LDSS + r * LDSS + s) * 4,
                       B + (size_t)(n0 + r) * K + k0 + s);
        }
        asm volatile("cp.async.commit_group;");
    };

    float acc[MT][NT][4];
    #pragma unroll
    for (int i = 0; i < MT; i++)
        #pragma unroll
        for (int j = 0; j < NT; j++)
            #pragma unroll
            for (int d = 0; d < 4; d++) acc[i][j][d] = 0.f;

    load_stage(0, 0);
    const int iters = K / BK;

    for (int it = 0; it < iters; it++) {
        if (it + 1 < iters) {
            load_stage(it + 1, (it + 1) & 1);
            asm volatile("cp.async.wait_group 1;" ::: "memory");
        } else {
            asm volatile("cp.async.wait_group 0;" ::: "memory");
        }
        __syncthreads();
        const uint32_t* Ab = As + (it & 1) * BM * LDSS;
        const uint32_t* Bb = Bs + (it & 1) * BN * LDSS;

        #pragma unroll
        for (int kk = 0; kk < BK; kk += 8) {
            uint32_t af[MT][4], bf[NT][2];
            #pragma unroll
            for (int mt = 0; mt < MT; mt++) {
                const uint32_t* pa = Ab + (wm + mt * 16 + lr) * LDSS + kk + lc;
                if (ATF) {
                    af[mt][0] = pa[0];
                    af[mt][1] = pa[8 * LDSS];
                    af[mt][2] = pa[4];
                    af[mt][3] = pa[8 * LDSS + 4];
                } else {
                    af[mt][0] = cvt_tf32(__uint_as_float(pa[0]));
                    af[mt][1] = cvt_tf32(__uint_as_float(pa[8 * LDSS]));
                    af[mt][2] = cvt_tf32(__uint_as_float(pa[4]));
                    af[mt][3] = cvt_tf32(__uint_as_float(pa[8 * LDSS + 4]));
                }
            }
            #pragma unroll
            for (int nt = 0; nt < NT; nt++) {
                const uint32_t* pb = Bb + (wn + nt * 8 + lr) * LDSS + kk + lc;
                bf[nt][0] = pb[0];
                bf[nt][1] = pb[4];
            }
            #pragma unroll
            for (int mt = 0; mt < MT; mt++)
                #pragma unroll
                for (int nt = 0; nt < NT; nt++)
                    mma_tf32(acc[mt][nt], af[mt], bf[nt]);
        }
        __syncthreads();
    }

    #pragma unroll
    for (int mt = 0; mt < MT; mt++) {
        int r0 = m0 + wm + mt * 16 + lr;
        #pragma unroll
        for (int nt = 0; nt < NT; nt++) {
            int c0 = n0 + wn + nt * 8 + 2 * lc;
            *(float2*)(C + (size_t)r0 * N + c0)       = make_float2(acc[mt][nt][0], acc[mt][nt][1]);
            *(float2*)(C + (size_t)(r0 + 8) * N + c0) = make_float2(acc[mt][nt][2], acc[mt][nt][3]);
        }
    }
}

#define GEMMA_SMEM ((2*64*68 + 2*32*68) * 4)
#define GEMMS_SMEM ((2*128*36 + 2*128*36) * 4)

// ---------------------------------------------------------------------------
// Row softmax for A (2048 x 256): warp-per-row, shfl-only; output tf32 bits.
// ---------------------------------------------------------------------------
__global__ void __launch_bounds__(256) k_softmaxA(
    const float* __restrict__ A, uint32_t* __restrict__ out)
{
    const int w = threadIdx.x >> 5, lane = threadIdx.x & 31;
    const int n = blockIdx.x * 8 + w;
    const float4* a4 = (const float4*)(A + (size_t)n * 256);
    float4 v0 = a4[lane];
    float4 v1 = a4[lane + 32];

    float m = fmaxf(fmaxf(fmaxf(v0.x, v0.y), fmaxf(v0.z, v0.w)),
                    fmaxf(fmaxf(v1.x, v1.y), fmaxf(v1.z, v1.w)));
    #pragma unroll
    for (int o = 16; o > 0; o >>= 1) m = fmaxf(m, __shfl_xor_sync(0xffffffffu, m, o));

    float e0 = __expf(v0.x - m), e1 = __expf(v0.y - m);
    float e2 = __expf(v0.z - m), e3 = __expf(v0.w - m);
    float e4 = __expf(v1.x - m), e5 = __expf(v1.y - m);
    float e6 = __expf(v1.z - m), e7 = __expf(v1.w - m);
    float s = ((e0 + e1) + (e2 + e3)) + ((e4 + e5) + (e6 + e7));
    #pragma unroll
    for (int o = 16; o > 0; o >>= 1) s += __shfl_xor_sync(0xffffffffu, s, o);
    float inv = 1.f / s;

    uint4* o4 = (uint4*)(out + (size_t)n * 256);
    o4[lane]      = make_uint4(cvt_tf32(e0 * inv), cvt_tf32(e1 * inv),
                               cvt_tf32(e2 * inv), cvt_tf32(e3 * inv));
    o4[lane + 32] = make_uint4(cvt_tf32(e4 * inv), cvt_tf32(e5 * inv),
                               cvt_tf32(e6 * inv), cvt_tf32(e7 * inv));
}

// ---------------------------------------------------------------------------
// Fused decode: one CTA per sample n, 192 threads = 6 warps, 3 CTAs/SM.
// stage1: tf32 (R10-measured swizzle). stage2: fp16 m16n8k16, Ua+smB as half
// (stride 56 halves = conflict-free 28*lr+lc bank map).
// ---------------------------------------------------------------------------
#define DEC_SMEM_U32 (192*48 + 192*48)
__global__ void __launch_bounds__(192, 3) k_dec(
    const float* __restrict__ S, const uint32_t* __restrict__ smB,
    const uint32_t* __restrict__ smC, float* __restrict__ out)
{
    extern __shared__ uint32_t smd[];
    uint32_t* Cs  = smd;              // smC [k][r3] swizzled (tf32); then Ua half
    uint32_t* UaH2 = smd;             // stage2: Ua half, stride 56 halves (28 u32)
    uint32_t* R2  = smd + 192 * 48;   // St (48x48 tf32); then smB half
    uint32_t* BH2 = smd + 192 * 48;   // stage2: smB half, stride 56 halves

    const int n = blockIdx.x, tid = threadIdx.x;
    const int w = tid >> 5, lane = tid & 31;
    const int lr = lane >> 2, lc = lane & 3;
    const int sw = (lr & 6) << 1;

    for (int i = tid; i < 2304; i += 192) {
        int r = i / 12, c = (i % 12) * 4;
        uint4 v = *(const uint4*)(smC + r * 48 + c);
        uint32_t* p = &Cs[r * 48 + (c ^ ((r & 6) << 1))];
        p[0] = v.x; p[1] = v.y; p[2] = v.z; p[3] = v.w;
    }
    const float* Sn = S + (size_t)n * 2304;
    for (int i = tid; i < 576; i += 192) {
        int r3 = i / 12, r2 = (i % 12) * 4;
        float4 v = *(const float4*)(Sn + r3 * 48 + r2);
        R2[(r2 + 0) * 48 + (r3 ^ (((r2 + 0) & 6) << 1))] = cvt_tf32(v.x);
        R2[(r2 + 1) * 48 + (r3 ^ (((r2 + 1) & 6) << 1))] = cvt_tf32(v.y);
        R2[(r2 + 2) * 48 + (r3 ^ (((r2 + 2) & 6) << 1))] = cvt_tf32(v.z);
        R2[(r2 + 3) * 48 + (r3 ^ (((r2 + 3) & 6) << 1))] = cvt_tf32(v.w);
    }
    __syncthreads();

    // stage1 (tf32): U[k][r2], warp w -> rows k in [w*32, w*32+32)
    float a1[2][6][4];
    #pragma unroll
    for (int i = 0; i < 2; i++)
        #pragma unroll
        for (int j = 0; j < 6; j++)
            #pragma unroll
            for (int d = 0; d < 4; d++) a1[i][j][d] = 0.f;

    #pragma unroll
    for (int kk = 0; kk < 48; kk += 8) {
        const int c0 = (kk ^ sw) + lc;
        const int c1 = ((kk + 4) ^ sw) + lc;
        uint32_t af[2][4], bf[6][2];
        #pragma unroll
        for (int mt = 0; mt < 2; mt++) {
            const uint32_t* pa = &Cs[(w * 32 + mt * 16 + lr) * 48];
            af[mt][0] = pa[c0]; af[mt][1] = pa[384 + c0];
            af[mt][2] = pa[c1]; af[mt][3] = pa[384 + c1];
        }
        #pragma unroll
        for (int nt = 0; nt < 6; nt++) {
            const uint32_t* pb = &R2[(nt * 8 + lr) * 48];
            bf[nt][0] = pb[c0]; bf[nt][1] = pb[c1];
        }
        #pragma unroll
        for (int mt = 0; mt < 2; mt++)
            #pragma unroll
            for (int nt = 0; nt < 6; nt++)
                mma_tf32(a1[mt][nt], af[mt], bf[nt]);
    }
    __syncthreads();   // smC + St reads done -> reuse regions for fp16 stage2

    // Ua -> half, stride 56 halves (28 u32): lane owns cols (nt*8+2lc, +1)
    #pragma unroll
    for (int mt = 0; mt < 2; mt++) {
        int k0 = w * 32 + mt * 16 + lr;
        #pragma unroll
        for (int nt = 0; nt < 6; nt++) {
            UaH2[k0 * 28 + nt * 4 + lc]       = packh2(a1[mt][nt][0], a1[mt][nt][1]);
            UaH2[(k0 + 8) * 28 + nt * 4 + lc] = packh2(a1[mt][nt][2], a1[mt][nt][3]);
        }
    }
    // smB (tf32 bits in gmem) -> half, stride 56 halves
    for (int i = tid; i < 2304; i += 192) {
        int r = i / 12, c = (i % 12) * 4;
        uint4 v = *(const uint4*)(smB + r * 48 + c);
        uint32_t* p = &BH2[r * 28 + (c >> 1)];
        p[0] = packh2(__uint_as_float(v.x), __uint_as_float(v.y));
        p[1] = packh2(__uint_as_float(v.z), __uint_as_float(v.w));
    }
    __syncthreads();

    // stage2 (fp16): out tile 192x192; warp grid 3(m) x 2(n); 8 lean passes.
    float* on = out + (size_t)n * 36864;
    const int wm = (w % 3) * 64;
    const int nb = (w / 3) * 24;
    #pragma unroll 1
    for (int np = 0; np < 4; np++) {
        const int wn = nb + np * 48;
        #pragma unroll 1
        for (int mp = 0; mp < 2; mp++) {
            const int mbase = wm + mp * 32;
            float a2[2][3][4];
            #pragma unroll
            for (int i = 0; i < 2; i++)
                #pragma unroll
                for (int j = 0; j < 3; j++)
                    #pragma unroll
                    for (int d = 0; d < 4; d++) a2[i][j][d] = 0.f;

            #pragma unroll
            for (int ks = 0; ks < 48; ks += 16) {
                uint32_t af[2][4], bf[3][2];
                #pragma unroll
                for (int mt = 0; mt < 2; mt++) {
                    const uint32_t* pa = &UaH2[(mbase + mt * 16 + lr) * 28 + (ks >> 1) + lc];
                    af[mt][0] = pa[0];            // rows lr,   k 2lc..
                    af[mt][1] = pa[8 * 28];       // rows lr+8
                    af[mt][2] = pa[4];            // k +8
                    af[mt][3] = pa[8 * 28 + 4];
                }
                #pragma unroll
                for (int nt = 0; nt < 3; nt++) {
                    const uint32_t* pb = &BH2[(wn + nt * 8 + lr) * 28 + (ks >> 1) + lc];
                    bf[nt][0] = pb[0];
                    bf[nt][1] = pb[4];
                }
                #pragma unroll
                for (int mt = 0; mt < 2; mt++)
                    #pragma unroll
                    for (int nt = 0; nt < 3; nt++)
                        mma_f16(a2[mt][nt], af[mt], bf[nt]);
            }
            #pragma unroll
            for (int mt = 0; mt < 2; mt++) {
                int row = mbase + mt * 16 + lr;
                #pragma unroll
                for (int nt = 0; nt < 3; nt++) {
                    int col = wn + nt * 8 + 2 * lc;
                    *(float2*)(on + (size_t)row * 192 + col) =
                        make_float2(a2[mt][nt][0], a2[mt][nt][1]);
                    *(float2*)(on + (size_t)(row + 8) * 192 + col) =
                        make_float2(a2[mt][nt][2], a2[mt][nt][3]);
                }
            }
        }
    }
}

// ---------------------------------------------------------------------------
// Launch pipeline (default stream -> sequential; graph-capturable)
// ---------------------------------------------------------------------------
extern "C" void kernel_launch(void* const* d_in, const int* in_sizes, int n_in,
                              void* d_out, int out_size)
{
    const float* X     = (const float*)d_in[0];
    const float* B     = (const float*)d_in[1];
    const float* C     = (const float*)d_in[2];
    const float* G     = (const float*)d_in[3];
    const float* B_inv = (const float*)d_in[4];
    const float* C_inv = (const float*)d_in[5];
    const float* G_inv = (const float*)d_in[6];
    float* out = (float*)d_out;

    float *pBuf2, *pA;
    uint32_t *pSmA, *pSmBT, *pSmCT, *pGt, *pGrt;
    cudaGetSymbolAddress((void**)&pBuf2, g_buf2);
    cudaGetSymbolAddress((void**)&pA,    g_Amat);
    cudaGetSymbolAddress((void**)&pSmA,  g_smA);
    cudaGetSymbolAddress((void**)&pSmBT, g_smBT);
    cudaGetSymbolAddress((void**)&pSmCT, g_smCT);
    cudaGetSymbolAddress((void**)&pGt,   g_Gt);
    cudaGetSymbolAddress((void**)&pGrt,  g_Grt);

    cudaFuncSetAttribute(k_enc, cudaFuncAttributeMaxDynamicSharedMemorySize, ENC_SMEM_U32 * 4);
    cudaFuncSetAttribute(k_dec, cudaFuncAttributeMaxDynamicSharedMemorySize, DEC_SMEM_U32 * 4);
    cudaFuncSetAttribute((const void*)k_gemm_tc_p<64, 32, 64, 4, 2, true, 1>,
                         cudaFuncAttributeMaxDynamicSharedMemorySize, GEMMA_SMEM);
    cudaFuncSetAttribute((const void*)k_gemm_tc_p<128, 128, 32, 4, 2, true, 2>,
                         cudaFuncAttributeMaxDynamicSharedMemorySize, GEMMS_SMEM);

    // encode + prep in one launch; Y emitted as tf32 bits into g_buf2
    k_enc<<<PREP_BLOCKS + NSAMP, 192, ENC_SMEM_U32 * 4>>>(
        X, B_inv, C_inv, (uint32_t*)pBuf2, G_inv, G, B, C, pGt, pGrt, pSmBT, pSmCT);

    // A = Y(tf32) @ G_inv^T(tf32); softmax rows (output tf32 bits)
    k_gemm_tc_p<64, 32, 64, 4, 2, true, 1><<<dim3(8, 32), 256, GEMMA_SMEM>>>(
        pBuf2, pGt, pA, 2048, 256, 2304);
    k_softmaxA<<<256, 256>>>(pA, pSmA);

    // S = smA(tf32) @ relu(G)^T(tf32) -> fp32; 128x128 tile, 2 CTAs/SM
    k_gemm_tc_p<128, 128, 32, 4, 2, true, 2><<<dim3(18, 16), 256, GEMMS_SMEM>>>(
        pSmA, pGrt, pBuf2, 2048, 2304, 256);

    // decode: out[n] = (smC @ S[n]) @ smB^T  (stage2 fp16)
    k_dec<<<2048, 192, DEC_SMEM_U32 * 4>>>(pBuf2, pSmBT, pSmCT, out);
}